// round 1
// baseline (speedup 1.0000x reference)
#include <cuda_runtime.h>

// DIN attention pooling, fused fp32 baseline.
// Inputs (metadata order):
// 0 item_emb [2048,128]  1 cat_emb [2048,64]
// 2 seq_items [2048,200,128] 3 seq_cats [2048,200,64]
// 4 seq_times [2048,200,32]  5 seq_beh [2048,200,32]
// 6 mask [2048,200]
// 7 W1 [448,256] 8 b1 [256] 9 W2 [256,1] 10 b2 [1]
// out [2048, 192] fp32

#define NB 2048
#define NS 200
#define HID 256
#define TS 8          // s-tile
#define NT (NS / TS)  // 25

// Per-b precomputed contribution U[b,h] = item@W1[0:128] + cat@W1[256:320] + b1
__device__ float g_U[NB * HID];

__global__ __launch_bounds__(256, 4)
void din_precompute_u(const float* __restrict__ item,
                      const float* __restrict__ cat,
                      const float* __restrict__ W1,
                      const float* __restrict__ b1) {
    __shared__ float sm[8][192];
    const int b0 = blockIdx.x * 8;
    const int tid = threadIdx.x;
    for (int i = tid; i < 8 * 192; i += 256) {
        int j = i / 192, k = i % 192;
        sm[j][k] = (k < 128) ? item[(b0 + j) * 128 + k]
                             : cat[(b0 + j) * 64 + (k - 128)];
    }
    __syncthreads();
    const int h = tid;
    float acc[8];
    const float bias = b1[h];
#pragma unroll
    for (int j = 0; j < 8; ++j) acc[j] = bias;
    const float* wi = W1 + h;              // rows 0..127 (item)
    const float* wc = W1 + 256 * HID + h;  // rows 256..319 (cat)
    for (int k = 0; k < 128; ++k) {
        float w = wi[k * HID];
#pragma unroll
        for (int j = 0; j < 8; ++j) acc[j] += w * sm[j][k];
    }
    for (int k = 0; k < 64; ++k) {
        float w = wc[k * HID];
#pragma unroll
        for (int j = 0; j < 8; ++j) acc[j] += w * sm[j][128 + k];
    }
#pragma unroll
    for (int j = 0; j < 8; ++j) g_U[(b0 + j) * HID + h] = acc[j];
}

__device__ __forceinline__ float sigmoidf_(float x) {
    return 1.0f / (1.0f + __expf(-x));
}

__global__ __launch_bounds__(256, 4)
void din_main(const float* __restrict__ seq_items,
              const float* __restrict__ seq_cats,
              const float* __restrict__ seq_times,
              const float* __restrict__ seq_beh,
              const float* __restrict__ mask,
              const float* __restrict__ W1,
              const float* __restrict__ W2,
              const float* __restrict__ b2,
              float* __restrict__ out) {
    // feat layout per s: [items(0:128) | cats(128:192) | times(192:224) | beh(224:256)]
    __shared__ float4 sfeat4[TS * 64];   // TS x 256 floats
    __shared__ float red[8][TS];
    __shared__ float sc_sm[TS];

    const int b = blockIdx.x;
    const int tid = threadIdx.x;
    const int lane = tid & 31;
    const int warp = tid >> 5;
    const int h = tid;

    const float u = g_U[b * HID + h];
    const float w2 = W2[h];
    const float bias2 = b2[0];
    // W1 seq rows: k<128 -> row 128+k (seq_items); k>=128 -> row 192+k (cats/times/beh)
    const float* p1 = W1 + 128 * HID + h;
    const float* p2 = W1 + 320 * HID + h;

    float acc_out = 0.0f;   // threads 0..191: output dim
    float tot = 0.0f;       // sum of scores (replicated)

    for (int t = 0; t < NT; ++t) {
        const int s0 = t * TS;
        // ---- cooperative feat load: TS*64 float4s ----
        for (int i = tid; i < TS * 64; i += 256) {
            int s = i >> 6, q = i & 63;
            int row = b * NS + s0 + s;
            float4 v;
            if (q < 32)      v = ((const float4*)(seq_items + (long)row * 128))[q];
            else if (q < 48) v = ((const float4*)(seq_cats  + (long)row * 64))[q - 32];
            else if (q < 56) v = ((const float4*)(seq_times + (long)row * 32))[q - 48];
            else             v = ((const float4*)(seq_beh   + (long)row * 32))[q - 56];
            sfeat4[s * 64 + q] = v;
        }
        __syncthreads();

        // ---- GEMM slice: acc[s] = feats[s,:] . W1seq[:,h] ----
        float acc[TS];
#pragma unroll
        for (int s = 0; s < TS; ++s) acc[s] = 0.0f;

#pragma unroll 2
        for (int k4 = 0; k4 < 32; ++k4) {   // k = 0..127
            float4 f[TS];
#pragma unroll
            for (int s = 0; s < TS; ++s) f[s] = sfeat4[s * 64 + k4];
#pragma unroll
            for (int j = 0; j < 4; ++j) {
                float w = p1[(k4 * 4 + j) * HID];
#pragma unroll
                for (int s = 0; s < TS; ++s) {
                    float fv = (j == 0) ? f[s].x : (j == 1) ? f[s].y
                             : (j == 2) ? f[s].z : f[s].w;
                    acc[s] += w * fv;
                }
            }
        }
#pragma unroll 2
        for (int k4 = 0; k4 < 32; ++k4) {   // k = 128..255
            float4 f[TS];
#pragma unroll
            for (int s = 0; s < TS; ++s) f[s] = sfeat4[s * 64 + 32 + k4];
#pragma unroll
            for (int j = 0; j < 4; ++j) {
                float w = p2[(k4 * 4 + j) * HID];
#pragma unroll
                for (int s = 0; s < TS; ++s) {
                    float fv = (j == 0) ? f[s].x : (j == 1) ? f[s].y
                             : (j == 2) ? f[s].z : f[s].w;
                    acc[s] += w * fv;
                }
            }
        }

        // ---- silu + W2 contribution, reduce over 256 h ----
        float contrib[TS];
#pragma unroll
        for (int s = 0; s < TS; ++s) {
            float x = u + acc[s];
            contrib[s] = x * sigmoidf_(x) * w2;
        }
#pragma unroll
        for (int off = 16; off; off >>= 1) {
#pragma unroll
            for (int s = 0; s < TS; ++s)
                contrib[s] += __shfl_xor_sync(0xffffffffu, contrib[s], off);
        }
        if (lane == 0) {
#pragma unroll
            for (int s = 0; s < TS; ++s) red[warp][s] = contrib[s];
        }
        __syncthreads();
        if (tid < TS) {
            float ssum = bias2;
#pragma unroll
            for (int w = 0; w < 8; ++w) ssum += red[w][tid];
            sc_sm[tid] = sigmoidf_(ssum) * mask[b * NS + s0 + tid];
        }
        __syncthreads();

        // ---- weighted accumulation (unnormalized) ----
        {
            const float* sfeat = (const float*)sfeat4;
#pragma unroll
            for (int s = 0; s < TS; ++s) {
                float w = sc_sm[s];
                tot += w;
                if (tid < 192) acc_out += w * sfeat[s * 256 + tid];
            }
        }
        __syncthreads();   // before next tile overwrites sfeat
    }

    if (tid < 192) out[b * 192 + tid] = acc_out / (tot + 1e-8f);
}

extern "C" void kernel_launch(void* const* d_in, const int* in_sizes, int n_in,
                              void* d_out, int out_size) {
    const float* item      = (const float*)d_in[0];
    const float* cat       = (const float*)d_in[1];
    const float* seq_items = (const float*)d_in[2];
    const float* seq_cats  = (const float*)d_in[3];
    const float* seq_times = (const float*)d_in[4];
    const float* seq_beh   = (const float*)d_in[5];
    const float* mask      = (const float*)d_in[6];
    const float* W1        = (const float*)d_in[7];
    const float* b1        = (const float*)d_in[8];
    const float* W2        = (const float*)d_in[9];
    const float* b2        = (const float*)d_in[10];
    float* out = (float*)d_out;

    din_precompute_u<<<NB / 8, 256>>>(item, cat, W1, b1);
    din_main<<<NB, 256>>>(seq_items, seq_cats, seq_times, seq_beh,
                          mask, W1, W2, b2, out);
}

// round 12
// speedup vs baseline: 2.0271x; 2.0271x over previous
#include <cuda_runtime.h>
#include <cuda_bf16.h>
#include <cstdint>

// DIN attention pooling — HMMA (mma.sync bf16 split-precision) version.
// Inputs (metadata order):
// 0 item_emb [2048,128]  1 cat_emb [2048,64]
// 2 seq_items [2048,200,128] 3 seq_cats [2048,200,64]
// 4 seq_times [2048,200,32]  5 seq_beh [2048,200,32]
// 6 mask [2048,200]
// 7 W1 [448,256] 8 b1 [256] 9 W2 [256,1] 10 b2 [1]
// out [2048,192] fp32

#define NB 2048
#define NS 200
#define HID 256

#define ROW_B 528            // padded SMEM row bytes (256 bf16 = 512B + 16B pad)
#define A_COMP 67584         // 128 rows * 528
#define B_COMP 33792         // 64 rows * 528

#define SM_A 0               // A hi at 0, A lo at A_COMP            (135168)
#define SM_B 135168          // B hi, B lo (+B_COMP)                 (67584)
#define SM_U 202752          // 256 f32
#define SM_W2 203776         // 256 f32
#define SM_SC 204800         // 128 f32
#define SMEM_BYTES 205312

// ---------------- global scratch ----------------
__device__ float g_U[NB * HID];                          // per-b bias term
__device__ __align__(16) __nv_bfloat16 g_Wh[HID * 256];  // [h][k] hi
__device__ __align__(16) __nv_bfloat16 g_Wl[HID * 256];  // [h][k] lo
__device__ float g_part[NB * 2 * 192];                   // per-CTA weighted partials
__device__ float g_stot[NB * 2];                         // per-CTA score totals
__device__ float g_w2b2[257];                            // packed [W2(256), b2]

// ---------------- PTX helpers ----------------
__device__ __forceinline__ uint32_t smem_u32(const void* p) {
    uint32_t a;
    asm("{ .reg .u64 t; cvta.to.shared.u64 t, %1; cvt.u32.u64 %0, t; }"
        : "=r"(a) : "l"(p));
    return a;
}
__device__ __forceinline__ void ldsm_x4(uint32_t* r, uint32_t addr) {
    asm volatile("ldmatrix.sync.aligned.m8n8.x4.shared.b16 {%0,%1,%2,%3}, [%4];"
        : "=r"(r[0]), "=r"(r[1]), "=r"(r[2]), "=r"(r[3]) : "r"(addr));
}
__device__ __forceinline__ void mma_bf16(float* c, const uint32_t* a,
                                         uint32_t b0, uint32_t b1) {
    asm volatile(
        "mma.sync.aligned.m16n8k16.row.col.f32.bf16.bf16.f32 "
        "{%0,%1,%2,%3}, {%4,%5,%6,%7}, {%8,%9}, {%0,%1,%2,%3};"
        : "+f"(c[0]), "+f"(c[1]), "+f"(c[2]), "+f"(c[3])
        : "r"(a[0]), "r"(a[1]), "r"(a[2]), "r"(a[3]), "r"(b0), "r"(b1));
}
__device__ __forceinline__ float sig_nat(float x) {
    return __fdividef(1.0f, 1.0f + __expf(-x));
}

// ---------------- prep kernels ----------------
__global__ __launch_bounds__(256, 4)
void din_precompute_u(const float* __restrict__ item,
                      const float* __restrict__ cat,
                      const float* __restrict__ W1,
                      const float* __restrict__ b1) {
    __shared__ float sm[8][192];
    const int b0 = blockIdx.x * 8;
    const int tid = threadIdx.x;
    for (int i = tid; i < 8 * 192; i += 256) {
        int j = i / 192, k = i % 192;
        sm[j][k] = (k < 128) ? item[(b0 + j) * 128 + k]
                             : cat[(b0 + j) * 64 + (k - 128)];
    }
    __syncthreads();
    const int h = tid;
    float acc[8];
    const float bias = b1[h];
#pragma unroll
    for (int j = 0; j < 8; ++j) acc[j] = bias;
    const float* wi = W1 + h;
    const float* wc = W1 + 256 * HID + h;
    for (int k = 0; k < 128; ++k) {
        float w = wi[k * HID];
#pragma unroll
        for (int j = 0; j < 8; ++j) acc[j] += w * sm[j][k];
    }
    for (int k = 0; k < 64; ++k) {
        float w = wc[k * HID];
#pragma unroll
        for (int j = 0; j < 8; ++j) acc[j] += w * sm[j][128 + k];
    }
#pragma unroll
    for (int j = 0; j < 8; ++j) g_U[(b0 + j) * HID + h] = acc[j];
}

// W1 seq rows -> [h][k] bf16 hi/lo.  k<128: W1 row 128+k; k>=128: row 192+k.
__global__ void din_wconvert(const float* __restrict__ W1) {
    int h = blockIdx.x;
    int k = threadIdx.x;
    int row = (k < 128) ? (128 + k) : (192 + k);
    float v = W1[row * HID + h];
    __nv_bfloat16 hb = __float2bfloat16(v);
    float hf = __bfloat162float(hb);
    g_Wh[h * 256 + k] = hb;
    g_Wl[h * 256 + k] = __float2bfloat16(v - hf);
}

__global__ void din_packw2(const float* __restrict__ W2, const float* __restrict__ b2) {
    int i = threadIdx.x;
    g_w2b2[i] = W2[i];
    if (i == 0) g_w2b2[256] = b2[0];
}

// ---------------- main kernel: one CTA = 128 s-rows of one b ----------------
__global__ __launch_bounds__(256, 1)
void din_mma(const float* __restrict__ seq_items,
             const float* __restrict__ seq_cats,
             const float* __restrict__ seq_times,
             const float* __restrict__ seq_beh,
             const float* __restrict__ mask,
             const float* __restrict__ b2p) {
    extern __shared__ char smem[];
    const uint32_t sb = smem_u32(smem);
    const int cta = blockIdx.x;
    const int b = cta >> 1;
    const int half = cta & 1;
    const int tid = threadIdx.x;
    const int wid = tid >> 5;
    const int lane = tid & 31;

    // ---- u, w2(+b2) into SMEM (b2p = packed [W2(256), b2]) ----
    ((float*)(smem + SM_U))[tid] = g_U[b * HID + tid];
    ((float*)(smem + SM_W2))[tid] = b2p[tid];
    const float b2v = b2p[256];

    // ---- A fill: 128 rows x 256 k -> bf16 hi/lo ----
    for (int i = tid; i < 8192; i += 256) {
        int r = i >> 6, q = i & 63;          // q: float4 index, k = q*4
        int s = half * 128 + r;
        float4 v = make_float4(0.f, 0.f, 0.f, 0.f);
        if (s < NS) {
            long row = (long)b * NS + s;
            if (q < 32)      v = ((const float4*)(seq_items + row * 128))[q];
            else if (q < 48) v = ((const float4*)(seq_cats  + row * 64))[q - 32];
            else if (q < 56) v = ((const float4*)(seq_times + row * 32))[q - 48];
            else             v = ((const float4*)(seq_beh   + row * 32))[q - 56];
        }
        __nv_bfloat162 hA = __floats2bfloat162_rn(v.x, v.y);
        __nv_bfloat162 hB = __floats2bfloat162_rn(v.z, v.w);
        float2 fA = __bfloat1622float2(hA);
        float2 fB = __bfloat1622float2(hB);
        __nv_bfloat162 lA = __floats2bfloat162_rn(v.x - fA.x, v.y - fA.y);
        __nv_bfloat162 lB = __floats2bfloat162_rn(v.z - fB.x, v.w - fB.y);
        uint32_t off = (uint32_t)(r * ROW_B + q * 8);
        *(uint2*)(smem + SM_A + off) =
            make_uint2(*(const uint32_t*)&hA, *(const uint32_t*)&hB);
        *(uint2*)(smem + SM_A + A_COMP + off) =
            make_uint2(*(const uint32_t*)&lA, *(const uint32_t*)&lB);
    }

    // ---- per-thread mma addressing ----
    // A ldmatrix.x4: lanes 0-15 -> rows 0..15, lanes 16-31 -> +16B (k8-15)
    const uint32_t a_addr0 = sb + SM_A + (uint32_t)((wid * 16 + (lane & 15)) * ROW_B)
                           + (uint32_t)((lane >> 4) << 4);
    // B ldmatrix.x4 (non-trans: W1 stored [n][k] row-major IS the col-major B op):
    // lanes 0-7: n0-7/k0-7 (b0, sub0); 8-15: n0-7/k8-15 (b1, sub0);
    // 16-23: n8-15/k0-7 (b0, sub1); 24-31: n8-15/k8-15 (b1, sub1)
    const uint32_t b_addr0 = sb + SM_B
                           + (uint32_t)(((lane & 7) + ((lane >> 4) << 3)) * ROW_B)
                           + (uint32_t)(((lane >> 3) & 1) << 4);

    float logit0 = 0.f, logit1 = 0.f;   // rows (wid*16 + lane/4) and +8

    // ---- N-chunks of 64 ----
    for (int nc = 0; nc < 4; ++nc) {
        __syncthreads();   // A ready (nc=0) / previous B consumed
        // B chunk: 64 h-rows x 256 k bf16 hi/lo (straight copy, rows padded)
        for (int i = tid; i < 2048; i += 256) {
            int n = i >> 5, q = i & 31;       // q: uint4 (8 bf16)
            *(uint4*)(smem + SM_B + n * ROW_B + q * 16) =
                *(const uint4*)(g_Wh + (nc * 64 + n) * 256 + q * 8);
            *(uint4*)(smem + SM_B + B_COMP + n * ROW_B + q * 16) =
                *(const uint4*)(g_Wl + (nc * 64 + n) * 256 + q * 8);
        }
        __syncthreads();

        float C[8][4];
#pragma unroll
        for (int t = 0; t < 8; ++t)
#pragma unroll
            for (int j = 0; j < 4; ++j) C[t][j] = 0.f;

#pragma unroll 4
        for (int kk = 0; kk < 16; ++kk) {
            uint32_t ah[4], al[4], bh[16], bl[16];
            ldsm_x4(ah, a_addr0 + kk * 32);
            ldsm_x4(al, a_addr0 + A_COMP + kk * 32);
#pragma unroll
            for (int p = 0; p < 4; ++p) {
                ldsm_x4(&bh[4 * p], b_addr0 + p * 16 * ROW_B + kk * 32);
                ldsm_x4(&bl[4 * p], b_addr0 + B_COMP + p * 16 * ROW_B + kk * 32);
            }
#pragma unroll
            for (int t = 0; t < 8; ++t)
                mma_bf16(C[t], ah, bh[t * 2], bh[t * 2 + 1]);
#pragma unroll
            for (int t = 0; t < 8; ++t)
                mma_bf16(C[t], al, bh[t * 2], bh[t * 2 + 1]);
#pragma unroll
            for (int t = 0; t < 8; ++t)
                mma_bf16(C[t], ah, bl[t * 2], bl[t * 2 + 1]);
        }

        // ---- fused epilogue: logit += silu(u + c) * w2 ----
        const float* u_sm = (const float*)(smem + SM_U);
        const float* w2_sm = (const float*)(smem + SM_W2);
#pragma unroll
        for (int t = 0; t < 8; ++t) {
            int h0 = nc * 64 + t * 8 + (lane & 3) * 2;
            float2 uu = *(const float2*)(u_sm + h0);
            float2 ww = *(const float2*)(w2_sm + h0);
            float x0 = uu.x + C[t][0], x1 = uu.y + C[t][1];
            float x2 = uu.x + C[t][2], x3 = uu.y + C[t][3];
            logit0 += x0 * sig_nat(x0) * ww.x + x1 * sig_nat(x1) * ww.y;
            logit1 += x2 * sig_nat(x2) * ww.x + x3 * sig_nat(x3) * ww.y;
        }
    }

    // ---- reduce logits across the 4 lanes sharing a row ----
    logit0 += __shfl_xor_sync(0xffffffffu, logit0, 1);
    logit0 += __shfl_xor_sync(0xffffffffu, logit0, 2);
    logit1 += __shfl_xor_sync(0xffffffffu, logit1, 1);
    logit1 += __shfl_xor_sync(0xffffffffu, logit1, 2);
    if ((lane & 3) == 0) {
        int r0 = wid * 16 + (lane >> 2);
        int s0 = half * 128 + r0;
        float sc0 = (s0 < NS) ? sig_nat(logit0 + b2v) * mask[b * NS + s0] : 0.f;
        float sc1 = (s0 + 8 < NS) ? sig_nat(logit1 + b2v) * mask[b * NS + s0 + 8] : 0.f;
        ((float*)(smem + SM_SC))[r0] = sc0;
        ((float*)(smem + SM_SC))[r0 + 8] = sc1;
    }
    __syncthreads();

    // ---- partial weighted sums over this CTA's 128 rows ----
    if (tid < 192) {
        const float* sc = (const float*)(smem + SM_SC);
        const __nv_bfloat16* hi = (const __nv_bfloat16*)(smem + SM_A);
        const __nv_bfloat16* lo = (const __nv_bfloat16*)(smem + SM_A + A_COMP);
        float acc = 0.f;
#pragma unroll 4
        for (int r = 0; r < 128; ++r) {
            float f = __bfloat162float(hi[r * (ROW_B / 2) + tid])
                    + __bfloat162float(lo[r * (ROW_B / 2) + tid]);
            acc += sc[r] * f;
        }
        g_part[cta * 192 + tid] = acc;
    }
    if (tid < 32) {
        const float* sc = (const float*)(smem + SM_SC);
        float v = sc[tid] + sc[tid + 32] + sc[tid + 64] + sc[tid + 96];
#pragma unroll
        for (int o = 16; o; o >>= 1) v += __shfl_xor_sync(0xffffffffu, v, o);
        if (tid == 0) g_stot[cta] = v;
    }
}

__global__ void din_combine(float* __restrict__ out) {
    int b = blockIdx.x, c = threadIdx.x;   // 192 threads
    float w = g_part[(2 * b) * 192 + c] + g_part[(2 * b + 1) * 192 + c];
    float s = g_stot[2 * b] + g_stot[2 * b + 1];
    out[b * 192 + c] = w / (s + 1e-8f);
}

extern "C" void kernel_launch(void* const* d_in, const int* in_sizes, int n_in,
                              void* d_out, int out_size) {
    const float* item      = (const float*)d_in[0];
    const float* cat       = (const float*)d_in[1];
    const float* seq_items = (const float*)d_in[2];
    const float* seq_cats  = (const float*)d_in[3];
    const float* seq_times = (const float*)d_in[4];
    const float* seq_beh   = (const float*)d_in[5];
    const float* mask      = (const float*)d_in[6];
    const float* W1        = (const float*)d_in[7];
    const float* b1        = (const float*)d_in[8];
    const float* W2        = (const float*)d_in[9];
    const float* b2        = (const float*)d_in[10];
    float* out = (float*)d_out;

    static bool attr_done = false;
    if (!attr_done) {
        cudaFuncSetAttribute(din_mma, cudaFuncAttributeMaxDynamicSharedMemorySize,
                             SMEM_BYTES);
        attr_done = true;
    }

    din_precompute_u<<<NB / 8, 256>>>(item, cat, W1, b1);
    din_wconvert<<<HID, 256>>>(W1);
    din_packw2<<<1, 256>>>(W2, b2);

    float* w2b2;
    cudaGetSymbolAddress((void**)&w2b2, g_w2b2);
    din_mma<<<NB * 2, 256, SMEM_BYTES>>>(seq_items, seq_cats, seq_times, seq_beh,
                                         mask, w2b2);
    din_combine<<<NB, 192>>>(out);
}

// round 13
// speedup vs baseline: 2.7213x; 1.3424x over previous
#include <cuda_runtime.h>
#include <cuda_bf16.h>
#include <cstdint>

// DIN attention pooling — HMMA bf16 split-precision, k-streamed cp.async pipeline.
// Inputs: 0 item[2048,128] 1 cat[2048,64] 2 seq_items[2048,200,128]
// 3 seq_cats[2048,200,64] 4 seq_times[2048,200,32] 5 seq_beh[2048,200,32]
// 6 mask[2048,200] 7 W1[448,256] 8 b1[256] 9 W2[256,1] 10 b2[1]  -> out[2048,192]

#define NB 2048
#define NS 200
#define HID 256

#define RS 48                 // SMEM row stride (32B data + 16B pad, LDSM conflict-free)
#define A_SZ  (128 * RS)      // 6144 per component
#define B_SZ  (256 * RS)      // 12288 per component
#define OFF_AH 0
#define OFF_AL A_SZ
#define OFF_BH (2 * A_SZ)
#define OFF_BL (2 * A_SZ + B_SZ)
#define STAGE  (2 * A_SZ + 2 * B_SZ)   // 36864
#define SM_U   (3 * STAGE)             // 110592: 256 f32
#define SM_W2  (SM_U + 1024)           // 256 f32
#define SM_LOG (SM_W2 + 1024)          // 256 f32 (128 rows x 2 halves)
#define SM_SC  (SM_LOG + 1024)         // 128 f32
#define SMEM_BYTES (SM_SC + 512)       // 114176

// ---------------- global scratch ----------------
__device__ float g_U[NB * HID];
__device__ __align__(16) __nv_bfloat16 g_Wh[HID * 256];  // [h][k] hi
__device__ __align__(16) __nv_bfloat16 g_Wl[HID * 256];  // [h][k] lo
__device__ float g_part[NB * 2 * 192];
__device__ float g_stot[NB * 2];
__device__ float g_w2b2[257];

// ---------------- PTX helpers ----------------
__device__ __forceinline__ uint32_t smem_u32(const void* p) {
    uint32_t a;
    asm("{ .reg .u64 t; cvta.to.shared.u64 t, %1; cvt.u32.u64 %0, t; }"
        : "=r"(a) : "l"(p));
    return a;
}
__device__ __forceinline__ void ldsm_x4(uint32_t* r, uint32_t addr) {
    asm volatile("ldmatrix.sync.aligned.m8n8.x4.shared.b16 {%0,%1,%2,%3}, [%4];"
        : "=r"(r[0]), "=r"(r[1]), "=r"(r[2]), "=r"(r[3]) : "r"(addr));
}
__device__ __forceinline__ void mma_bf16(float* c, const uint32_t* a,
                                         uint32_t b0, uint32_t b1) {
    asm volatile(
        "mma.sync.aligned.m16n8k16.row.col.f32.bf16.bf16.f32 "
        "{%0,%1,%2,%3}, {%4,%5,%6,%7}, {%8,%9}, {%0,%1,%2,%3};"
        : "+f"(c[0]), "+f"(c[1]), "+f"(c[2]), "+f"(c[3])
        : "r"(a[0]), "r"(a[1]), "r"(a[2]), "r"(a[3]), "r"(b0), "r"(b1));
}
__device__ __forceinline__ void cp16(uint32_t dst, const void* src) {
    asm volatile("cp.async.cg.shared.global [%0], [%1], 16;"
        :: "r"(dst), "l"(src));
}
#define CP_COMMIT() asm volatile("cp.async.commit_group;")
#define CP_WAIT(n)  asm volatile("cp.async.wait_group %0;" :: "n"(n))

__device__ __forceinline__ float sig_nat(float x) {
    return __fdividef(1.0f, 1.0f + __expf(-x));
}

// feat gather: k in [0,256) with k16-aligned regions
__device__ __forceinline__ float4 feat4(const float* it, const float* ca,
                                        const float* ti, const float* be,
                                        long row, int k) {
    if (k < 128) return *(const float4*)(it + row * 128 + k);
    if (k < 192) return *(const float4*)(ca + row * 64 + (k - 128));
    if (k < 224) return *(const float4*)(ti + row * 32 + (k - 192));
    return *(const float4*)(be + row * 32 + (k - 224));
}

// ---------------- prep kernels ----------------
__global__ __launch_bounds__(256, 4)
void din_precompute_u(const float* __restrict__ item,
                      const float* __restrict__ cat,
                      const float* __restrict__ W1,
                      const float* __restrict__ b1) {
    __shared__ float sm[8][192];
    const int b0 = blockIdx.x * 8;
    const int tid = threadIdx.x;
    for (int i = tid; i < 8 * 192; i += 256) {
        int j = i / 192, k = i % 192;
        sm[j][k] = (k < 128) ? item[(b0 + j) * 128 + k]
                             : cat[(b0 + j) * 64 + (k - 128)];
    }
    __syncthreads();
    const int h = tid;
    float acc[8];
    const float bias = b1[h];
#pragma unroll
    for (int j = 0; j < 8; ++j) acc[j] = bias;
    const float* wi = W1 + h;
    const float* wc = W1 + 256 * HID + h;
    for (int k = 0; k < 128; ++k) {
        float w = wi[k * HID];
#pragma unroll
        for (int j = 0; j < 8; ++j) acc[j] += w * sm[j][k];
    }
    for (int k = 0; k < 64; ++k) {
        float w = wc[k * HID];
#pragma unroll
        for (int j = 0; j < 8; ++j) acc[j] += w * sm[j][128 + k];
    }
#pragma unroll
    for (int j = 0; j < 8; ++j) g_U[(b0 + j) * HID + h] = acc[j];
}

__global__ void din_wconvert(const float* __restrict__ W1) {
    int h = blockIdx.x;
    int k = threadIdx.x;
    int row = (k < 128) ? (128 + k) : (192 + k);
    float v = W1[row * HID + h];
    __nv_bfloat16 hb = __float2bfloat16(v);
    float hf = __bfloat162float(hb);
    g_Wh[h * 256 + k] = hb;
    g_Wl[h * 256 + k] = __float2bfloat16(v - hf);
}

__global__ void din_packw2(const float* __restrict__ W2, const float* __restrict__ b2) {
    int i = threadIdx.x;
    g_w2b2[i] = W2[i];
    if (i == 0) g_w2b2[256] = b2[0];
}

// ---------------- A-slice convert+store ----------------
__device__ __forceinline__ void sts_a(char* smem, int stage, int ar, int aq, float4 v) {
    __nv_bfloat162 hA = __floats2bfloat162_rn(v.x, v.y);
    __nv_bfloat162 hB = __floats2bfloat162_rn(v.z, v.w);
    float2 fA = __bfloat1622float2(hA);
    float2 fB = __bfloat1622float2(hB);
    __nv_bfloat162 lA = __floats2bfloat162_rn(v.x - fA.x, v.y - fA.y);
    __nv_bfloat162 lB = __floats2bfloat162_rn(v.z - fB.x, v.w - fB.y);
    uint32_t off = (uint32_t)(stage * STAGE + ar * RS + aq * 8);
    *(uint2*)(smem + OFF_AH + off) =
        make_uint2(*(const uint32_t*)&hA, *(const uint32_t*)&hB);
    *(uint2*)(smem + OFF_AL + off) =
        make_uint2(*(const uint32_t*)&lA, *(const uint32_t*)&lB);
}

// ---------------- main kernel: CTA = 128 s-rows of one b ----------------
__global__ __launch_bounds__(512, 1)
void din_mma2(const float* __restrict__ seq_items,
              const float* __restrict__ seq_cats,
              const float* __restrict__ seq_times,
              const float* __restrict__ seq_beh,
              const float* __restrict__ mask,
              const float* __restrict__ b2p) {
    extern __shared__ char smem[];
    const uint32_t sb = smem_u32(smem);
    const int cta = blockIdx.x;
    const int b = cta >> 1;
    const int half = cta & 1;
    const int tid = threadIdx.x;
    const int wid = tid >> 5;
    const int lane = tid & 31;
    const int mt = wid >> 1;     // m-tile 0..7 (16 rows each)
    const int nh = wid & 1;      // n-half 0..1 (128 cols each)

    if (tid < 256) {
        ((float*)(smem + SM_U))[tid] = g_U[b * HID + tid];
        ((float*)(smem + SM_W2))[tid] = b2p[tid];
    }
    const float b2v = b2p[256];

    // A mapping: thread -> (row, k4-group)
    const int ar = tid >> 2, aq = tid & 3;
    const long arow = (long)b * NS + half * 128 + ar;
    const bool a_ok = (half * 128 + ar) < NS;
    // B mapping: thread -> (n-row, 16B-half)
    const int br = tid >> 1, bq = tid & 1;
    const uint32_t b_dst_off = (uint32_t)(br * RS + bq * 16);
    const int b_src_off = br * 256 + bq * 8;

    // ---- prologue: stages 0,1 direct; A pending for 2,3 ----
#pragma unroll
    for (int p = 0; p < 2; ++p) {
        float4 v = make_float4(0.f, 0.f, 0.f, 0.f);
        if (a_ok) v = feat4(seq_items, seq_cats, seq_times, seq_beh, arow, p * 16 + aq * 4);
        sts_a(smem, p, ar, aq, v);
        cp16(sb + p * STAGE + OFF_BH + b_dst_off, g_Wh + p * 16 + b_src_off);
        cp16(sb + p * STAGE + OFF_BL + b_dst_off, g_Wl + p * 16 + b_src_off);
        CP_COMMIT();
    }
    float4 vA0 = make_float4(0.f, 0.f, 0.f, 0.f);
    float4 vA1 = make_float4(0.f, 0.f, 0.f, 0.f);
    if (a_ok) {
        vA0 = feat4(seq_items, seq_cats, seq_times, seq_beh, arow, 2 * 16 + aq * 4);
        vA1 = feat4(seq_items, seq_cats, seq_times, seq_beh, arow, 3 * 16 + aq * 4);
    }

    float C[16][4];
#pragma unroll
    for (int t = 0; t < 16; ++t)
#pragma unroll
        for (int j = 0; j < 4; ++j) C[t][j] = 0.f;

    const uint32_t a_off = (uint32_t)((mt * 16 + (lane & 15)) * RS + ((lane >> 4) << 4));
    const uint32_t b_off = (uint32_t)((nh * 128 + (lane & 7) + ((lane >> 4) << 3)) * RS
                                      + (((lane >> 3) & 1) << 4));

    // ---- mainloop: 16 k16 stages ----
    for (int kk = 0; kk < 16; ++kk) {
        if (kk < 14) { CP_WAIT(1); } else { CP_WAIT(0); }
        __syncthreads();

        const int pf = kk + 2;
        if (pf < 16) {
            const int st = pf % 3;
            sts_a(smem, st, ar, aq, vA0);
            vA0 = vA1;
            cp16(sb + st * STAGE + OFF_BH + b_dst_off, g_Wh + pf * 16 + b_src_off);
            cp16(sb + st * STAGE + OFF_BL + b_dst_off, g_Wl + pf * 16 + b_src_off);
            CP_COMMIT();
            if (kk + 4 < 16 && a_ok)
                vA1 = feat4(seq_items, seq_cats, seq_times, seq_beh, arow,
                            (kk + 4) * 16 + aq * 4);
        }

        const uint32_t st = sb + (uint32_t)((kk % 3) * STAGE);
        uint32_t ah[4], al[4];
        ldsm_x4(ah, st + OFF_AH + a_off);
        ldsm_x4(al, st + OFF_AL + a_off);
#pragma unroll
        for (int p = 0; p < 8; ++p) {
            uint32_t bh[4], bl[4];
            ldsm_x4(bh, st + OFF_BH + b_off + (uint32_t)(p * 16 * RS));
            ldsm_x4(bl, st + OFF_BL + b_off + (uint32_t)(p * 16 * RS));
            mma_bf16(C[2 * p],     ah, bh[0], bh[1]);
            mma_bf16(C[2 * p + 1], ah, bh[2], bh[3]);
            mma_bf16(C[2 * p],     al, bh[0], bh[1]);
            mma_bf16(C[2 * p + 1], al, bh[2], bh[3]);
            mma_bf16(C[2 * p],     ah, bl[0], bl[1]);
            mma_bf16(C[2 * p + 1], ah, bl[2], bl[3]);
        }
    }

    // ---- silu/W2 epilogue: per-row logits over this warp's n-half ----
    {
        const float* u_sm = (const float*)(smem + SM_U);
        const float* w2_sm = (const float*)(smem + SM_W2);
        float logit0 = 0.f, logit1 = 0.f;
#pragma unroll
        for (int t = 0; t < 16; ++t) {
            int h0 = nh * 128 + t * 8 + (lane & 3) * 2;
            float2 uu = *(const float2*)(u_sm + h0);
            float2 ww = *(const float2*)(w2_sm + h0);
            float x0 = uu.x + C[t][0], x1 = uu.y + C[t][1];
            float x2 = uu.x + C[t][2], x3 = uu.y + C[t][3];
            logit0 += x0 * sig_nat(x0) * ww.x + x1 * sig_nat(x1) * ww.y;
            logit1 += x2 * sig_nat(x2) * ww.x + x3 * sig_nat(x3) * ww.y;
        }
        logit0 += __shfl_xor_sync(0xffffffffu, logit0, 1);
        logit0 += __shfl_xor_sync(0xffffffffu, logit0, 2);
        logit1 += __shfl_xor_sync(0xffffffffu, logit1, 1);
        logit1 += __shfl_xor_sync(0xffffffffu, logit1, 2);
        if ((lane & 3) == 0) {
            int r0 = mt * 16 + (lane >> 2);
            ((float*)(smem + SM_LOG))[r0 * 2 + nh] = logit0;
            ((float*)(smem + SM_LOG))[(r0 + 8) * 2 + nh] = logit1;
        }
    }
    __syncthreads();

    if (tid < 128) {
        const float* lg = (const float*)(smem + SM_LOG);
        float l = lg[tid * 2] + lg[tid * 2 + 1] + b2v;
        int s = half * 128 + tid;
        ((float*)(smem + SM_SC))[tid] =
            (s < NS) ? sig_nat(l) * mask[b * NS + s] : 0.f;
    }
    __syncthreads();

    // ---- weighted partial sums (gmem re-read, L2-hot) ----
    const int rows = (half == 0) ? 128 : (NS - 128);
    if (tid < 192) {
        const float* sc = (const float*)(smem + SM_SC);
        const float* src;
        int stride;
        if (tid < 128) {
            src = seq_items + ((long)b * NS + half * 128) * 128 + tid;
            stride = 128;
        } else {
            src = seq_cats + ((long)b * NS + half * 128) * 64 + (tid - 128);
            stride = 64;
        }
        float acc = 0.f;
#pragma unroll 4
        for (int r = 0; r < rows; ++r) acc += sc[r] * src[(long)r * stride];
        g_part[cta * 192 + tid] = acc;
    }
    if (tid < 32) {
        const float* sc = (const float*)(smem + SM_SC);
        float v = sc[tid] + sc[tid + 32] + sc[tid + 64] + sc[tid + 96];
#pragma unroll
        for (int o = 16; o; o >>= 1) v += __shfl_xor_sync(0xffffffffu, v, o);
        if (tid == 0) g_stot[cta] = v;
    }
}

__global__ void din_combine(float* __restrict__ out) {
    int b = blockIdx.x, c = threadIdx.x;   // 192 threads
    float w = g_part[(2 * b) * 192 + c] + g_part[(2 * b + 1) * 192 + c];
    float s = g_stot[2 * b] + g_stot[2 * b + 1];
    out[b * 192 + c] = w / (s + 1e-8f);
}

extern "C" void kernel_launch(void* const* d_in, const int* in_sizes, int n_in,
                              void* d_out, int out_size) {
    const float* item      = (const float*)d_in[0];
    const float* cat       = (const float*)d_in[1];
    const float* seq_items = (const float*)d_in[2];
    const float* seq_cats  = (const float*)d_in[3];
    const float* seq_times = (const float*)d_in[4];
    const float* seq_beh   = (const float*)d_in[5];
    const float* mask      = (const float*)d_in[6];
    const float* W1        = (const float*)d_in[7];
    const float* b1        = (const float*)d_in[8];
    const float* W2        = (const float*)d_in[9];
    const float* b2        = (const float*)d_in[10];
    float* out = (float*)d_out;

    static bool attr_done = false;
    if (!attr_done) {
        cudaFuncSetAttribute(din_mma2, cudaFuncAttributeMaxDynamicSharedMemorySize,
                             SMEM_BYTES);
        attr_done = true;
    }

    din_precompute_u<<<NB / 8, 256>>>(item, cat, W1, b1);
    din_wconvert<<<HID, 256>>>(W1);
    din_packw2<<<1, 256>>>(W2, b2);

    float* w2b2;
    cudaGetSymbolAddress((void**)&w2b2, g_w2b2);
    din_mma2<<<NB * 2, 512, SMEM_BYTES>>>(seq_items, seq_cats, seq_times, seq_beh,
                                          mask, w2b2);
    din_combine<<<NB, 192>>>(out);
}

// round 14
// speedup vs baseline: 3.4739x; 1.2766x over previous
#include <cuda_runtime.h>
#include <cuda_fp16.h>
#include <cstdint>

// DIN attention pooling — HMMA fp16 A-split 2-product, k-streamed cp.async pipeline,
// M=64 CTAs for 2 CTAs/SM overlap.
// Inputs: 0 item[2048,128] 1 cat[2048,64] 2 seq_items[2048,200,128]
// 3 seq_cats[2048,200,64] 4 seq_times[2048,200,32] 5 seq_beh[2048,200,32]
// 6 mask[2048,200] 7 W1[448,256] 8 b1[256] 9 W2[256,1] 10 b2[1]  -> out[2048,192]

#define NB 2048
#define NS 200
#define HID 256
#define MT 64                 // s-rows per CTA

#define RS 48                 // SMEM row stride (32B data + 16B pad, LDSM conflict-free)
#define A_SZ (MT * RS)        // 3072 per component
#define B_SZ (256 * RS)       // 12288
#define OFF_AH 0
#define OFF_AL A_SZ
#define OFF_B  (2 * A_SZ)
#define STAGE  (2 * A_SZ + B_SZ)       // 18432
#define SM_U   (3 * STAGE)             // 55296: 256 f32
#define SM_W2  (SM_U + 1024)           // 256 f32
#define SM_LOG (SM_W2 + 1024)          // 64 x 2 f32
#define SM_SC  (SM_LOG + 512)          // 64 f32
#define SM_RED (SM_SC + 256)           // 192 f32
#define SMEM_BYTES (SM_RED + 768)      // 58624

// ---------------- global scratch ----------------
__device__ float g_U[NB * HID];
__device__ __align__(16) __half g_W[HID * 256];   // [h][k] fp16
__device__ float g_part[NB * 4 * 192];
__device__ float g_stot[NB * 4];
__device__ float g_w2b2[257];

// ---------------- PTX helpers ----------------
__device__ __forceinline__ uint32_t smem_u32(const void* p) {
    uint32_t a;
    asm("{ .reg .u64 t; cvta.to.shared.u64 t, %1; cvt.u32.u64 %0, t; }"
        : "=r"(a) : "l"(p));
    return a;
}
__device__ __forceinline__ void ldsm_x4(uint32_t* r, uint32_t addr) {
    asm volatile("ldmatrix.sync.aligned.m8n8.x4.shared.b16 {%0,%1,%2,%3}, [%4];"
        : "=r"(r[0]), "=r"(r[1]), "=r"(r[2]), "=r"(r[3]) : "r"(addr));
}
__device__ __forceinline__ void mma_fp16(float* c, const uint32_t* a,
                                         uint32_t b0, uint32_t b1) {
    asm volatile(
        "mma.sync.aligned.m16n8k16.row.col.f32.f16.f16.f32 "
        "{%0,%1,%2,%3}, {%4,%5,%6,%7}, {%8,%9}, {%0,%1,%2,%3};"
        : "+f"(c[0]), "+f"(c[1]), "+f"(c[2]), "+f"(c[3])
        : "r"(a[0]), "r"(a[1]), "r"(a[2]), "r"(a[3]), "r"(b0), "r"(b1));
}
__device__ __forceinline__ void cp16(uint32_t dst, const void* src) {
    asm volatile("cp.async.cg.shared.global [%0], [%1], 16;"
        :: "r"(dst), "l"(src));
}
#define CP_COMMIT() asm volatile("cp.async.commit_group;")
#define CP_WAIT(n)  asm volatile("cp.async.wait_group %0;" :: "n"(n))

__device__ __forceinline__ float sig_nat(float x) {
    return __fdividef(1.0f, 1.0f + __expf(-x));
}

// feat gather: k in [0,256), regions k16-aligned
__device__ __forceinline__ float4 feat4(const float* it, const float* ca,
                                        const float* ti, const float* be,
                                        long row, int k) {
    if (k < 128) return *(const float4*)(it + row * 128 + k);
    if (k < 192) return *(const float4*)(ca + row * 64 + (k - 128));
    if (k < 224) return *(const float4*)(ti + row * 32 + (k - 192));
    return *(const float4*)(be + row * 32 + (k - 224));
}

// ---------------- prep kernels ----------------
__global__ __launch_bounds__(256, 4)
void din_precompute_u(const float* __restrict__ item,
                      const float* __restrict__ cat,
                      const float* __restrict__ W1,
                      const float* __restrict__ b1) {
    __shared__ float sm[8][192];
    const int b0 = blockIdx.x * 8;
    const int tid = threadIdx.x;
    for (int i = tid; i < 8 * 192; i += 256) {
        int j = i / 192, k = i % 192;
        sm[j][k] = (k < 128) ? item[(b0 + j) * 128 + k]
                             : cat[(b0 + j) * 64 + (k - 128)];
    }
    __syncthreads();
    const int h = tid;
    float acc[8];
    const float bias = b1[h];
#pragma unroll
    for (int j = 0; j < 8; ++j) acc[j] = bias;
    const float* wi = W1 + h;
    const float* wc = W1 + 256 * HID + h;
    for (int k = 0; k < 128; ++k) {
        float w = wi[k * HID];
#pragma unroll
        for (int j = 0; j < 8; ++j) acc[j] += w * sm[j][k];
    }
    for (int k = 0; k < 64; ++k) {
        float w = wc[k * HID];
#pragma unroll
        for (int j = 0; j < 8; ++j) acc[j] += w * sm[j][128 + k];
    }
#pragma unroll
    for (int j = 0; j < 8; ++j) g_U[(b0 + j) * HID + h] = acc[j];
}

// W1 seq rows -> [h][k] fp16. k<128: row 128+k (seq_items); else row 192+k.
__global__ void din_wconvert(const float* __restrict__ W1) {
    int h = blockIdx.x;
    int k = threadIdx.x;
    int row = (k < 128) ? (128 + k) : (192 + k);
    g_W[h * 256 + k] = __float2half_rn(W1[row * HID + h]);
}

__global__ void din_packw2(const float* __restrict__ W2, const float* __restrict__ b2) {
    int i = threadIdx.x;
    g_w2b2[i] = W2[i];
    if (i == 0) g_w2b2[256] = b2[0];
}

// ---------------- A-slice convert+store (fp16 hi/lo) ----------------
__device__ __forceinline__ void sts_a(char* smem, int stage, int ar, int aq, float4 v) {
    __half2 h0 = __floats2half2_rn(v.x, v.y);
    __half2 h1 = __floats2half2_rn(v.z, v.w);
    float2 f0 = __half22float2(h0);
    float2 f1 = __half22float2(h1);
    __half2 l0 = __floats2half2_rn(v.x - f0.x, v.y - f0.y);
    __half2 l1 = __floats2half2_rn(v.z - f1.x, v.w - f1.y);
    uint32_t off = (uint32_t)(stage * STAGE + ar * RS + aq * 8);
    *(uint2*)(smem + OFF_AH + off) =
        make_uint2(*(const uint32_t*)&h0, *(const uint32_t*)&h1);
    *(uint2*)(smem + OFF_AL + off) =
        make_uint2(*(const uint32_t*)&l0, *(const uint32_t*)&l1);
}

// ---------------- main kernel: CTA = 64 s-rows of one b ----------------
__global__ __launch_bounds__(256, 2)
void din_mma3(const float* __restrict__ seq_items,
              const float* __restrict__ seq_cats,
              const float* __restrict__ seq_times,
              const float* __restrict__ seq_beh,
              const float* __restrict__ mask,
              const float* __restrict__ b2p) {
    extern __shared__ char smem[];
    const uint32_t sb = smem_u32(smem);
    const int cta = blockIdx.x;
    const int b = cta >> 2;
    const int m0 = (cta & 3) * MT;
    const int tid = threadIdx.x;
    const int wid = tid >> 5;
    const int lane = tid & 31;
    const int mt = wid >> 1;     // m-tile 0..3 (16 rows)
    const int nh = wid & 1;      // n-half 0..1 (128 cols)

    ((float*)(smem + SM_U))[tid] = g_U[b * HID + tid];
    ((float*)(smem + SM_W2))[tid] = b2p[tid];
    if (tid < 192) ((float*)(smem + SM_RED))[tid] = 0.f;
    const float b2v = b2p[256];

    // A mapping: thread -> (row, k4-group)
    const int ar = tid >> 2, aq = tid & 3;
    const long arow = (long)b * NS + m0 + ar;
    const bool a_ok = (m0 + ar) < NS;
    // B mapping: thread -> n-row; 2x16B per stage
    const uint32_t b_dst = (uint32_t)(tid * RS);
    const int b_src = tid * 256;

    // ---- prologue: stages 0,1 direct ----
#pragma unroll
    for (int p = 0; p < 2; ++p) {
        float4 v = make_float4(0.f, 0.f, 0.f, 0.f);
        if (a_ok) v = feat4(seq_items, seq_cats, seq_times, seq_beh, arow, p * 16 + aq * 4);
        sts_a(smem, p, ar, aq, v);
        cp16(sb + p * STAGE + OFF_B + b_dst, g_W + b_src + p * 16);
        cp16(sb + p * STAGE + OFF_B + b_dst + 16, g_W + b_src + p * 16 + 8);
        CP_COMMIT();
    }
    float4 vA0 = make_float4(0.f, 0.f, 0.f, 0.f);
    float4 vA1 = make_float4(0.f, 0.f, 0.f, 0.f);
    if (a_ok) {
        vA0 = feat4(seq_items, seq_cats, seq_times, seq_beh, arow, 2 * 16 + aq * 4);
        vA1 = feat4(seq_items, seq_cats, seq_times, seq_beh, arow, 3 * 16 + aq * 4);
    }

    float C[16][4];
#pragma unroll
    for (int t = 0; t < 16; ++t)
#pragma unroll
        for (int j = 0; j < 4; ++j) C[t][j] = 0.f;

    const uint32_t a_off = (uint32_t)((mt * 16 + (lane & 15)) * RS + ((lane >> 4) << 4));
    const uint32_t b_off = (uint32_t)((nh * 128 + (lane & 7) + ((lane >> 4) << 3)) * RS
                                      + (((lane >> 3) & 1) << 4));

    // ---- mainloop: 16 k16 stages, 3-deep ring ----
    for (int kk = 0; kk < 16; ++kk) {
        if (kk < 14) { CP_WAIT(1); } else { CP_WAIT(0); }
        __syncthreads();

        const int pf = kk + 2;
        if (pf < 16) {
            const int st = pf % 3;
            sts_a(smem, st, ar, aq, vA0);
            vA0 = vA1;
            cp16(sb + st * STAGE + OFF_B + b_dst, g_W + b_src + pf * 16);
            cp16(sb + st * STAGE + OFF_B + b_dst + 16, g_W + b_src + pf * 16 + 8);
            CP_COMMIT();
            if (kk + 4 < 16 && a_ok)
                vA1 = feat4(seq_items, seq_cats, seq_times, seq_beh, arow,
                            (kk + 4) * 16 + aq * 4);
        }

        const uint32_t st = sb + (uint32_t)((kk % 3) * STAGE);
        uint32_t ah[4], al[4];
        ldsm_x4(ah, st + OFF_AH + a_off);
        ldsm_x4(al, st + OFF_AL + a_off);
#pragma unroll
        for (int p = 0; p < 8; ++p) {
            uint32_t bh[4];
            ldsm_x4(bh, st + OFF_B + b_off + (uint32_t)(p * 16 * RS));
            mma_fp16(C[2 * p],     ah, bh[0], bh[1]);
            mma_fp16(C[2 * p + 1], ah, bh[2], bh[3]);
            mma_fp16(C[2 * p],     al, bh[0], bh[1]);
            mma_fp16(C[2 * p + 1], al, bh[2], bh[3]);
        }
    }

    // ---- silu/W2 epilogue: per-row logits over this warp's n-half ----
    {
        const float* u_sm = (const float*)(smem + SM_U);
        const float* w2_sm = (const float*)(smem + SM_W2);
        float logit0 = 0.f, logit1 = 0.f;
#pragma unroll
        for (int t = 0; t < 16; ++t) {
            int h0 = nh * 128 + t * 8 + (lane & 3) * 2;
            float2 uu = *(const float2*)(u_sm + h0);
            float2 ww = *(const float2*)(w2_sm + h0);
            float x0 = uu.x + C[t][0], x1 = uu.y + C[t][1];
            float x2 = uu.x + C[t][2], x3 = uu.y + C[t][3];
            logit0 += x0 * sig_nat(x0) * ww.x + x1 * sig_nat(x1) * ww.y;
            logit1 += x2 * sig_nat(x2) * ww.x + x3 * sig_nat(x3) * ww.y;
        }
        logit0 += __shfl_xor_sync(0xffffffffu, logit0, 1);
        logit0 += __shfl_xor_sync(0xffffffffu, logit0, 2);
        logit1 += __shfl_xor_sync(0xffffffffu, logit1, 1);
        logit1 += __shfl_xor_sync(0xffffffffu, logit1, 2);
        if ((lane & 3) == 0) {
            int r0 = mt * 16 + (lane >> 2);
            ((float*)(smem + SM_LOG))[r0 * 2 + nh] = logit0;
            ((float*)(smem + SM_LOG))[(r0 + 8) * 2 + nh] = logit1;
        }
    }
    __syncthreads();

    if (tid < MT) {
        const float* lg = (const float*)(smem + SM_LOG);
        float l = lg[tid * 2] + lg[tid * 2 + 1] + b2v;
        int s = m0 + tid;
        ((float*)(smem + SM_SC))[tid] =
            (s < NS) ? sig_nat(l) * mask[b * NS + s] : 0.f;
    }
    __syncthreads();

    // ---- weighted partial sums: warp-cooperative, smem atomic reduce ----
    {
        const float* sc = (const float*)(smem + SM_SC);
        float* red = (float*)(smem + SM_RED);
        float acc[6];
#pragma unroll
        for (int j = 0; j < 6; ++j) acc[j] = 0.f;
#pragma unroll 2
        for (int i = 0; i < 8; ++i) {
            int r = wid * 8 + i;
            int s = m0 + r;
            if (s < NS) {
                float w = sc[r];
                const float* it = seq_items + ((long)b * NS + s) * 128;
                const float* ca = seq_cats + ((long)b * NS + s) * 64;
#pragma unroll
                for (int j = 0; j < 4; ++j) acc[j] += w * it[lane + 32 * j];
#pragma unroll
                for (int j = 4; j < 6; ++j) acc[j] += w * ca[lane + 32 * (j - 4)];
            }
        }
#pragma unroll
        for (int j = 0; j < 6; ++j) atomicAdd(red + lane + 32 * j, acc[j]);
    }
    __syncthreads();

    if (tid < 192) g_part[cta * 192 + tid] = ((const float*)(smem + SM_RED))[tid];
    if (tid < 32) {
        const float* sc = (const float*)(smem + SM_SC);
        float v = sc[tid] + sc[tid + 32];
#pragma unroll
        for (int o = 16; o; o >>= 1) v += __shfl_xor_sync(0xffffffffu, v, o);
        if (tid == 0) g_stot[cta] = v;
    }
}

__global__ void din_combine(float* __restrict__ out) {
    int b = blockIdx.x, c = threadIdx.x;   // 192 threads
    float w = g_part[(4 * b) * 192 + c] + g_part[(4 * b + 1) * 192 + c]
            + g_part[(4 * b + 2) * 192 + c] + g_part[(4 * b + 3) * 192 + c];
    float s = g_stot[4 * b] + g_stot[4 * b + 1] + g_stot[4 * b + 2] + g_stot[4 * b + 3];
    out[b * 192 + c] = w / (s + 1e-8f);
}

extern "C" void kernel_launch(void* const* d_in, const int* in_sizes, int n_in,
                              void* d_out, int out_size) {
    const float* item      = (const float*)d_in[0];
    const float* cat       = (const float*)d_in[1];
    const float* seq_items = (const float*)d_in[2];
    const float* seq_cats  = (const float*)d_in[3];
    const float* seq_times = (const float*)d_in[4];
    const float* seq_beh   = (const float*)d_in[5];
    const float* mask      = (const float*)d_in[6];
    const float* W1        = (const float*)d_in[7];
    const float* b1        = (const float*)d_in[8];
    const float* W2        = (const float*)d_in[9];
    const float* b2        = (const float*)d_in[10];
    float* out = (float*)d_out;

    static bool attr_done = false;
    if (!attr_done) {
        cudaFuncSetAttribute(din_mma3, cudaFuncAttributeMaxDynamicSharedMemorySize,
                             SMEM_BYTES);
        attr_done = true;
    }

    din_precompute_u<<<NB / 8, 256>>>(item, cat, W1, b1);
    din_wconvert<<<HID, 256>>>(W1);
    din_packw2<<<1, 256>>>(W2, b2);

    float* w2b2;
    cudaGetSymbolAddress((void**)&w2b2, g_w2b2);
    din_mma3<<<NB * 4, 256, SMEM_BYTES>>>(seq_items, seq_cats, seq_times, seq_beh,
                                          mask, w2b2);
    din_combine<<<NB, 192>>>(out);
}

// round 15
// speedup vs baseline: 4.5487x; 1.3094x over previous
#include <cuda_runtime.h>
#include <cuda_fp16.h>
#include <cstdint>

// DIN attention pooling — HMMA fp16 single-product, A-resident SMEM,
// B cp.async ring with k32 super-stages. M=64 CTAs, 2 CTAs/SM.
// Inputs: 0 item[2048,128] 1 cat[2048,64] 2 seq_items[2048,200,128]
// 3 seq_cats[2048,200,64] 4 seq_times[2048,200,32] 5 seq_beh[2048,200,32]
// 6 mask[2048,200] 7 W1[448,256] 8 b1[256] 9 W2[256,1] 10 b2[1] -> out[2048,192]

#define NB 2048
#define NS 200
#define HID 256
#define MT 64                 // s-rows per CTA

#define ARS 528               // A row stride (512B data + 16B pad; ldsm conflict-free)
#define A_RES (MT * ARS)      // 33792
#define BRS 48                // B row stride per k16 sub-slice
#define BS1 (256 * BRS)       // 12288 per k16 sub-slice
#define SS_SZ (2 * BS1)       // 24576 per k32 super-stage
#define OFF_B A_RES           // B ring: 3 super-stages
#define SM_U   (A_RES + 3 * SS_SZ)     // 107520: 256 f32
#define SM_W2  (SM_U + 1024)
#define SM_LOG (SM_W2 + 1024)          // 64 x 2 f32
#define SM_SC  (SM_LOG + 512)          // 64 f32
#define SM_RED (SM_SC + 256)           // 192 f32
#define SMEM_BYTES (SM_RED + 768)      // 111104

// ---------------- global scratch ----------------
__device__ float g_U[NB * HID];
__device__ __align__(16) __half g_W[HID * 256];   // [h][k] fp16
__device__ float g_part[NB * 4 * 192];
__device__ float g_stot[NB * 4];
__device__ float g_w2b2[257];

// ---------------- PTX helpers ----------------
__device__ __forceinline__ uint32_t smem_u32(const void* p) {
    uint32_t a;
    asm("{ .reg .u64 t; cvta.to.shared.u64 t, %1; cvt.u32.u64 %0, t; }"
        : "=r"(a) : "l"(p));
    return a;
}
__device__ __forceinline__ void ldsm_x4(uint32_t* r, uint32_t addr) {
    asm volatile("ldmatrix.sync.aligned.m8n8.x4.shared.b16 {%0,%1,%2,%3}, [%4];"
        : "=r"(r[0]), "=r"(r[1]), "=r"(r[2]), "=r"(r[3]) : "r"(addr));
}
__device__ __forceinline__ void mma_fp16(float* c, const uint32_t* a,
                                         uint32_t b0, uint32_t b1) {
    asm volatile(
        "mma.sync.aligned.m16n8k16.row.col.f32.f16.f16.f32 "
        "{%0,%1,%2,%3}, {%4,%5,%6,%7}, {%8,%9}, {%0,%1,%2,%3};"
        : "+f"(c[0]), "+f"(c[1]), "+f"(c[2]), "+f"(c[3])
        : "r"(a[0]), "r"(a[1]), "r"(a[2]), "r"(a[3]), "r"(b0), "r"(b1));
}
__device__ __forceinline__ void cp16(uint32_t dst, const void* src) {
    asm volatile("cp.async.cg.shared.global [%0], [%1], 16;"
        :: "r"(dst), "l"(src));
}
#define CP_COMMIT() asm volatile("cp.async.commit_group;")
#define CP_WAIT(n)  asm volatile("cp.async.wait_group %0;" :: "n"(n))

__device__ __forceinline__ float sig_nat(float x) {
    return __fdividef(1.0f, 1.0f + __expf(-x));
}

// feat gather: k in [0,256), regions k16-aligned
__device__ __forceinline__ float4 feat4(const float* it, const float* ca,
                                        const float* ti, const float* be,
                                        long row, int k) {
    if (k < 128) return *(const float4*)(it + row * 128 + k);
    if (k < 192) return *(const float4*)(ca + row * 64 + (k - 128));
    if (k < 224) return *(const float4*)(ti + row * 32 + (k - 192));
    return *(const float4*)(be + row * 32 + (k - 224));
}

// ---------------- prep kernels ----------------
__global__ __launch_bounds__(256, 4)
void din_precompute_u(const float* __restrict__ item,
                      const float* __restrict__ cat,
                      const float* __restrict__ W1,
                      const float* __restrict__ b1) {
    __shared__ float sm[8][192];
    const int b0 = blockIdx.x * 8;
    const int tid = threadIdx.x;
    for (int i = tid; i < 8 * 192; i += 256) {
        int j = i / 192, k = i % 192;
        sm[j][k] = (k < 128) ? item[(b0 + j) * 128 + k]
                             : cat[(b0 + j) * 64 + (k - 128)];
    }
    __syncthreads();
    const int h = tid;
    float acc[8];
    const float bias = b1[h];
#pragma unroll
    for (int j = 0; j < 8; ++j) acc[j] = bias;
    const float* wi = W1 + h;
    const float* wc = W1 + 256 * HID + h;
    for (int k = 0; k < 128; ++k) {
        float w = wi[k * HID];
#pragma unroll
        for (int j = 0; j < 8; ++j) acc[j] += w * sm[j][k];
    }
    for (int k = 0; k < 64; ++k) {
        float w = wc[k * HID];
#pragma unroll
        for (int j = 0; j < 8; ++j) acc[j] += w * sm[j][128 + k];
    }
#pragma unroll
    for (int j = 0; j < 8; ++j) g_U[(b0 + j) * HID + h] = acc[j];
}

// W1 seq rows -> [h][k] fp16. k<128: row 128+k (seq_items); else row 192+k.
__global__ void din_wconvert(const float* __restrict__ W1) {
    int h = blockIdx.x;
    int k = threadIdx.x;
    int row = (k < 128) ? (128 + k) : (192 + k);
    g_W[h * 256 + k] = __float2half_rn(W1[row * HID + h]);
}

__global__ void din_packw2(const float* __restrict__ W2, const float* __restrict__ b2) {
    int i = threadIdx.x;
    g_w2b2[i] = W2[i];
    if (i == 0) g_w2b2[256] = b2[0];
}

// ---------------- main kernel: CTA = 64 s-rows of one b ----------------
__global__ __launch_bounds__(256, 2)
void din_mma4(const float* __restrict__ seq_items,
              const float* __restrict__ seq_cats,
              const float* __restrict__ seq_times,
              const float* __restrict__ seq_beh,
              const float* __restrict__ mask,
              const float* __restrict__ b2p) {
    extern __shared__ char smem[];
    const uint32_t sb = smem_u32(smem);
    const int cta = blockIdx.x;
    const int b = cta >> 2;
    const int m0 = (cta & 3) * MT;
    const int tid = threadIdx.x;
    const int wid = tid >> 5;
    const int lane = tid & 31;
    const int mt = wid >> 1;     // m-tile 0..3 (16 rows)
    const int nh = wid & 1;      // n-half 0..1 (128 cols)

    ((float*)(smem + SM_U))[tid] = g_U[b * HID + tid];
    ((float*)(smem + SM_W2))[tid] = b2p[tid];
    if (tid < 192) ((float*)(smem + SM_RED))[tid] = 0.f;
    const float b2v = b2p[256];

    // ---- B ring prologue: super-stages 0,1 (k32 each) ----
    const uint32_t b_dst = (uint32_t)(tid * BRS);
    const __half* b_src = g_W + tid * 256;
#pragma unroll
    for (int ss = 0; ss < 2; ++ss) {
        uint32_t d = sb + OFF_B + ss * SS_SZ + b_dst;
        const __half* s = b_src + ss * 32;
        cp16(d, s);            cp16(d + 16, s + 8);
        cp16(d + BS1, s + 16); cp16(d + BS1 + 16, s + 24);
        CP_COMMIT();
    }

    // ---- A resident fill: 64 rows x 256 k -> fp16 (hi only) ----
    {
        const int ar = tid >> 2, aq = tid & 3;
        const long arow = (long)b * NS + m0 + ar;
        const bool a_ok = (m0 + ar) < NS;
        char* abase = smem + ar * ARS + aq * 8;
#pragma unroll
        for (int kk = 0; kk < 16; ++kk) {
            float4 v = make_float4(0.f, 0.f, 0.f, 0.f);
            if (a_ok) v = feat4(seq_items, seq_cats, seq_times, seq_beh,
                                arow, kk * 16 + aq * 4);
            __half2 h0 = __floats2half2_rn(v.x, v.y);
            __half2 h1 = __floats2half2_rn(v.z, v.w);
            *(uint2*)(abase + kk * 32) =
                make_uint2(*(const uint32_t*)&h0, *(const uint32_t*)&h1);
        }
    }

    float C[16][4];
#pragma unroll
    for (int t = 0; t < 16; ++t)
#pragma unroll
        for (int j = 0; j < 4; ++j) C[t][j] = 0.f;

    const uint32_t a_off = sb + (uint32_t)((mt * 16 + (lane & 15)) * ARS
                                           + ((lane >> 4) << 4));
    const uint32_t b_off = (uint32_t)((nh * 128 + (lane & 7) + ((lane >> 4) << 3)) * BRS
                                      + (((lane >> 3) & 1) << 4));

    // ---- mainloop: 8 k32 super-stages, 3-deep B ring ----
    for (int ss = 0; ss < 8; ++ss) {
        if (ss < 6) { CP_WAIT(1); } else { CP_WAIT(0); }
        __syncthreads();   // also covers A-resident visibility at ss=0

        const int pf = ss + 2;
        if (pf < 8) {
            uint32_t d = sb + OFF_B + (pf % 3) * SS_SZ + b_dst;
            const __half* s = b_src + pf * 32;
            cp16(d, s);            cp16(d + 16, s + 8);
            cp16(d + BS1, s + 16); cp16(d + BS1 + 16, s + 24);
            CP_COMMIT();
        }

        const uint32_t bstage = sb + OFF_B + (uint32_t)((ss % 3) * SS_SZ);
#pragma unroll
        for (int sub = 0; sub < 2; ++sub) {
            const int kk = ss * 2 + sub;
            uint32_t ah[4];
            ldsm_x4(ah, a_off + (uint32_t)(kk * 32));
            const uint32_t bb = bstage + (uint32_t)(sub * BS1) + b_off;
#pragma unroll
            for (int p = 0; p < 8; ++p) {
                uint32_t bh[4];
                ldsm_x4(bh, bb + (uint32_t)(p * 16 * BRS));
                mma_fp16(C[2 * p],     ah, bh[0], bh[1]);
                mma_fp16(C[2 * p + 1], ah, bh[2], bh[3]);
            }
        }
    }

    // ---- silu/W2 epilogue: per-row logits over this warp's n-half ----
    {
        const float* u_sm = (const float*)(smem + SM_U);
        const float* w2_sm = (const float*)(smem + SM_W2);
        float logit0 = 0.f, logit1 = 0.f;
#pragma unroll
        for (int t = 0; t < 16; ++t) {
            int h0 = nh * 128 + t * 8 + (lane & 3) * 2;
            float2 uu = *(const float2*)(u_sm + h0);
            float2 ww = *(const float2*)(w2_sm + h0);
            float x0 = uu.x + C[t][0], x1 = uu.y + C[t][1];
            float x2 = uu.x + C[t][2], x3 = uu.y + C[t][3];
            logit0 += x0 * sig_nat(x0) * ww.x + x1 * sig_nat(x1) * ww.y;
            logit1 += x2 * sig_nat(x2) * ww.x + x3 * sig_nat(x3) * ww.y;
        }
        logit0 += __shfl_xor_sync(0xffffffffu, logit0, 1);
        logit0 += __shfl_xor_sync(0xffffffffu, logit0, 2);
        logit1 += __shfl_xor_sync(0xffffffffu, logit1, 1);
        logit1 += __shfl_xor_sync(0xffffffffu, logit1, 2);
        if ((lane & 3) == 0) {
            int r0 = mt * 16 + (lane >> 2);
            ((float*)(smem + SM_LOG))[r0 * 2 + nh] = logit0;
            ((float*)(smem + SM_LOG))[(r0 + 8) * 2 + nh] = logit1;
        }
    }
    __syncthreads();

    if (tid < MT) {
        const float* lg = (const float*)(smem + SM_LOG);
        float l = lg[tid * 2] + lg[tid * 2 + 1] + b2v;
        int s = m0 + tid;
        ((float*)(smem + SM_SC))[tid] =
            (s < NS) ? sig_nat(l) * mask[b * NS + s] : 0.f;
    }
    __syncthreads();

    // ---- weighted partial sums: warp-cooperative, smem atomic reduce ----
    {
        const float* sc = (const float*)(smem + SM_SC);
        float* red = (float*)(smem + SM_RED);
        float acc[6];
#pragma unroll
        for (int j = 0; j < 6; ++j) acc[j] = 0.f;
#pragma unroll 2
        for (int i = 0; i < 8; ++i) {
            int r = wid * 8 + i;
            int s = m0 + r;
            if (s < NS) {
                float w = sc[r];
                const float* it = seq_items + ((long)b * NS + s) * 128;
                const float* ca = seq_cats + ((long)b * NS + s) * 64;
#pragma unroll
                for (int j = 0; j < 4; ++j) acc[j] += w * it[lane + 32 * j];
#pragma unroll
                for (int j = 4; j < 6; ++j) acc[j] += w * ca[lane + 32 * (j - 4)];
            }
        }
#pragma unroll
        for (int j = 0; j < 6; ++j) atomicAdd(red + lane + 32 * j, acc[j]);
    }
    __syncthreads();

    if (tid < 192) g_part[cta * 192 + tid] = ((const float*)(smem + SM_RED))[tid];
    if (tid < 32) {
        const float* sc = (const float*)(smem + SM_SC);
        float v = sc[tid] + sc[tid + 32];
#pragma unroll
        for (int o = 16; o; o >>= 1) v += __shfl_xor_sync(0xffffffffu, v, o);
        if (tid == 0) g_stot[cta] = v;
    }
}

__global__ void din_combine(float* __restrict__ out) {
    int b = blockIdx.x, c = threadIdx.x;   // 192 threads
    float w = g_part[(4 * b) * 192 + c] + g_part[(4 * b + 1) * 192 + c]
            + g_part[(4 * b + 2) * 192 + c] + g_part[(4 * b + 3) * 192 + c];
    float s = g_stot[4 * b] + g_stot[4 * b + 1] + g_stot[4 * b + 2] + g_stot[4 * b + 3];
    out[b * 192 + c] = w / (s + 1e-8f);
}

extern "C" void kernel_launch(void* const* d_in, const int* in_sizes, int n_in,
                              void* d_out, int out_size) {
    const float* item      = (const float*)d_in[0];
    const float* cat       = (const float*)d_in[1];
    const float* seq_items = (const float*)d_in[2];
    const float* seq_cats  = (const float*)d_in[3];
    const float* seq_times = (const float*)d_in[4];
    const float* seq_beh   = (const float*)d_in[5];
    const float* mask      = (const float*)d_in[6];
    const float* W1        = (const float*)d_in[7];
    const float* b1        = (const float*)d_in[8];
    const float* W2        = (const float*)d_in[9];
    const float* b2        = (const float*)d_in[10];
    float* out = (float*)d_out;

    static bool attr_done = false;
    if (!attr_done) {
        cudaFuncSetAttribute(din_mma4, cudaFuncAttributeMaxDynamicSharedMemorySize,
                             SMEM_BYTES);
        attr_done = true;
    }

    din_precompute_u<<<NB / 8, 256>>>(item, cat, W1, b1);
    din_wconvert<<<HID, 256>>>(W1);
    din_packw2<<<1, 256>>>(W2, b2);

    float* w2b2;
    cudaGetSymbolAddress((void**)&w2b2, g_w2b2);
    din_mma4<<<NB * 4, 256, SMEM_BYTES>>>(seq_items, seq_cats, seq_times, seq_beh,
                                          mask, w2b2);
    din_combine<<<NB, 192>>>(out);
}

// round 16
// speedup vs baseline: 7.3964x; 1.6260x over previous
#include <cuda_runtime.h>
#include <cuda_fp16.h>
#include <cstdint>

// DIN attention pooling — HMMA fp16, A-resident SMEM, B as fragment-packed
// gmem loaded via LDG.64 (L1-resident, no cp.async, no mainloop barriers).
// Inputs: 0 item[2048,128] 1 cat[2048,64] 2 seq_items[2048,200,128]
// 3 seq_cats[2048,200,64] 4 seq_times[2048,200,32] 5 seq_beh[2048,200,32]
// 6 mask[2048,200] 7 W1[448,256] 8 b1[256] 9 W2[256,1] 10 b2[1] -> out[2048,192]

#define NB 2048
#define NS 200
#define HID 256
#define MT 64                 // s-rows per CTA

#define ARS 528               // A row stride (512B data + 16B pad; ldsm conflict-free)
#define A_RES (MT * ARS)      // 33792
#define SM_U   A_RES          // 256 f32
#define SM_W2  (SM_U + 1024)
#define SM_LOG (SM_W2 + 1024)          // 64 rows x 4 nq f32
#define SM_SC  (SM_LOG + 1024)         // 64 f32
#define SM_RED (SM_SC + 256)           // 192 f32
#define SMEM_BYTES (SM_RED + 768)      // 37888

// ---------------- global scratch ----------------
__device__ float g_U[NB * HID];
// B fragments: [n8(32)][k16(16)][lane(32)] -> uint2 {b0,b1}
__device__ __align__(16) uint2 g_Wf[32 * 16 * 32];
__device__ float g_part[NB * 4 * 192];
__device__ float g_stot[NB * 4];
__device__ float g_w2b2[257];

// ---------------- PTX helpers ----------------
__device__ __forceinline__ uint32_t smem_u32(const void* p) {
    uint32_t a;
    asm("{ .reg .u64 t; cvta.to.shared.u64 t, %1; cvt.u32.u64 %0, t; }"
        : "=r"(a) : "l"(p));
    return a;
}
__device__ __forceinline__ void ldsm_x4(uint32_t* r, uint32_t addr) {
    asm volatile("ldmatrix.sync.aligned.m8n8.x4.shared.b16 {%0,%1,%2,%3}, [%4];"
        : "=r"(r[0]), "=r"(r[1]), "=r"(r[2]), "=r"(r[3]) : "r"(addr));
}
__device__ __forceinline__ void mma_fp16(float* c, const uint32_t* a,
                                         uint32_t b0, uint32_t b1) {
    asm volatile(
        "mma.sync.aligned.m16n8k16.row.col.f32.f16.f16.f32 "
        "{%0,%1,%2,%3}, {%4,%5,%6,%7}, {%8,%9}, {%0,%1,%2,%3};"
        : "+f"(c[0]), "+f"(c[1]), "+f"(c[2]), "+f"(c[3])
        : "r"(a[0]), "r"(a[1]), "r"(a[2]), "r"(a[3]), "r"(b0), "r"(b1));
}
__device__ __forceinline__ float sig_nat(float x) {
    return __fdividef(1.0f, 1.0f + __expf(-x));
}

// feat gather: k in [0,256), regions k16-aligned
__device__ __forceinline__ float4 feat4(const float* it, const float* ca,
                                        const float* ti, const float* be,
                                        long row, int k) {
    if (k < 128) return *(const float4*)(it + row * 128 + k);
    if (k < 192) return *(const float4*)(ca + row * 64 + (k - 128));
    if (k < 224) return *(const float4*)(ti + row * 32 + (k - 192));
    return *(const float4*)(be + row * 32 + (k - 224));
}

// ---------------- prep kernels ----------------
__global__ __launch_bounds__(256, 4)
void din_precompute_u(const float* __restrict__ item,
                      const float* __restrict__ cat,
                      const float* __restrict__ W1,
                      const float* __restrict__ b1) {
    __shared__ float sm[8][192];
    const int b0 = blockIdx.x * 8;
    const int tid = threadIdx.x;
    for (int i = tid; i < 8 * 192; i += 256) {
        int j = i / 192, k = i % 192;
        sm[j][k] = (k < 128) ? item[(b0 + j) * 128 + k]
                             : cat[(b0 + j) * 64 + (k - 128)];
    }
    __syncthreads();
    const int h = tid;
    float acc[8];
    const float bias = b1[h];
#pragma unroll
    for (int j = 0; j < 8; ++j) acc[j] = bias;
    const float* wi = W1 + h;
    const float* wc = W1 + 256 * HID + h;
    for (int k = 0; k < 128; ++k) {
        float w = wi[k * HID];
#pragma unroll
        for (int j = 0; j < 8; ++j) acc[j] += w * sm[j][k];
    }
    for (int k = 0; k < 64; ++k) {
        float w = wc[k * HID];
#pragma unroll
        for (int j = 0; j < 8; ++j) acc[j] += w * sm[j][128 + k];
    }
#pragma unroll
    for (int j = 0; j < 8; ++j) g_U[(b0 + j) * HID + h] = acc[j];
}

// Pack W1 seq rows into mma B-fragment order.
// Logical W[n][k] = W1[(k<128 ? 128+k : 192+k)][n] (n = hidden unit).
// Fragment for (n8, k16), lane t: b0 = {W[n][k0], W[n][k0+1]},
// b1 = {W[n][k0+8], W[n][k0+9]}, with n = n8*8 + t/4, k0 = k16*16 + (t%4)*2.
__global__ void din_wfrag(const float* __restrict__ W1) {
    const int tile = blockIdx.x;        // 0..511 = n8*16 + k16
    const int n8 = tile >> 4, k16 = tile & 15;
    const int lane = threadIdx.x;
    const int n = n8 * 8 + (lane >> 2);
    const int k0 = k16 * 16 + (lane & 3) * 2;
    auto w = [&](int k) -> float {
        int row = (k < 128) ? (128 + k) : (192 + k);
        return W1[row * HID + n];
    };
    __half2 b0 = __floats2half2_rn(w(k0), w(k0 + 1));
    __half2 b1 = __floats2half2_rn(w(k0 + 8), w(k0 + 9));
    g_Wf[tile * 32 + lane] = make_uint2(*(const uint32_t*)&b0, *(const uint32_t*)&b1);
}

__global__ void din_packw2(const float* __restrict__ W2, const float* __restrict__ b2) {
    int i = threadIdx.x;
    g_w2b2[i] = W2[i];
    if (i == 0) g_w2b2[256] = b2[0];
}

// ---------------- main kernel: CTA = 64 s-rows of one b ----------------
__global__ __launch_bounds__(256, 2)
void din_mma5(const float* __restrict__ seq_items,
              const float* __restrict__ seq_cats,
              const float* __restrict__ seq_times,
              const float* __restrict__ seq_beh,
              const float* __restrict__ mask,
              const float* __restrict__ b2p) {
    extern __shared__ char smem[];
    const uint32_t sb = smem_u32(smem);
    const int cta = blockIdx.x;
    const int b = cta >> 2;
    const int m0 = (cta & 3) * MT;
    const int tid = threadIdx.x;
    const int wid = tid >> 5;
    const int lane = tid & 31;
    const int mt2 = wid >> 2;    // m-half 0..1 (32 rows)
    const int nq = wid & 3;      // n-quarter 0..3 (64 cols)

    ((float*)(smem + SM_U))[tid] = g_U[b * HID + tid];
    ((float*)(smem + SM_W2))[tid] = b2p[tid];
    if (tid < 192) ((float*)(smem + SM_RED))[tid] = 0.f;
    const float b2v = b2p[256];

    // ---- A resident fill: 64 rows x 256 k -> fp16 ----
    {
        const int ar = tid >> 2, aq = tid & 3;
        const long arow = (long)b * NS + m0 + ar;
        const bool a_ok = (m0 + ar) < NS;
        char* abase = smem + ar * ARS + aq * 8;
#pragma unroll
        for (int kk = 0; kk < 16; ++kk) {
            float4 v = make_float4(0.f, 0.f, 0.f, 0.f);
            if (a_ok) v = feat4(seq_items, seq_cats, seq_times, seq_beh,
                                arow, kk * 16 + aq * 4);
            __half2 h0 = __floats2half2_rn(v.x, v.y);
            __half2 h1 = __floats2half2_rn(v.z, v.w);
            *(uint2*)(abase + kk * 32) =
                make_uint2(*(const uint32_t*)&h0, *(const uint32_t*)&h1);
        }
    }
    __syncthreads();

    float C[2][8][4];
#pragma unroll
    for (int m2 = 0; m2 < 2; ++m2)
#pragma unroll
        for (int p = 0; p < 8; ++p)
#pragma unroll
            for (int j = 0; j < 4; ++j) C[m2][p][j] = 0.f;

    const uint32_t a_off = sb + (uint32_t)((mt2 * 32 + (lane & 15)) * ARS
                                           + ((lane >> 4) << 4));
    // B fragment base for this warp's n-quarter (n8 tiles nq*8 .. nq*8+7)
    const uint2* bf_base = g_Wf + (size_t)(nq * 8) * 16 * 32 + lane;

    // ---- mainloop: 16 k16 steps, no barriers ----
#pragma unroll 2
    for (int kk = 0; kk < 16; ++kk) {
        uint2 bf[8];
#pragma unroll
        for (int p = 0; p < 8; ++p)
            bf[p] = __ldg(bf_base + (size_t)(p * 16 + kk) * 32);
        uint32_t a0[4], a1[4];
        ldsm_x4(a0, a_off + (uint32_t)(kk * 32));
        ldsm_x4(a1, a_off + (uint32_t)(16 * ARS + kk * 32));
#pragma unroll
        for (int p = 0; p < 8; ++p) {
            mma_fp16(C[0][p], a0, bf[p].x, bf[p].y);
            mma_fp16(C[1][p], a1, bf[p].x, bf[p].y);
        }
    }

    // ---- silu/W2 epilogue: per-row logits over this warp's n-quarter ----
    {
        const float* u_sm = (const float*)(smem + SM_U);
        const float* w2_sm = (const float*)(smem + SM_W2);
        float* lg = (float*)(smem + SM_LOG);
#pragma unroll
        for (int m2 = 0; m2 < 2; ++m2) {
            float l0 = 0.f, l1 = 0.f;
#pragma unroll
            for (int p = 0; p < 8; ++p) {
                int h0 = nq * 64 + p * 8 + (lane & 3) * 2;
                float2 uu = *(const float2*)(u_sm + h0);
                float2 ww = *(const float2*)(w2_sm + h0);
                float x0 = uu.x + C[m2][p][0], x1 = uu.y + C[m2][p][1];
                float x2 = uu.x + C[m2][p][2], x3 = uu.y + C[m2][p][3];
                l0 += x0 * sig_nat(x0) * ww.x + x1 * sig_nat(x1) * ww.y;
                l1 += x2 * sig_nat(x2) * ww.x + x3 * sig_nat(x3) * ww.y;
            }
            l0 += __shfl_xor_sync(0xffffffffu, l0, 1);
            l0 += __shfl_xor_sync(0xffffffffu, l0, 2);
            l1 += __shfl_xor_sync(0xffffffffu, l1, 1);
            l1 += __shfl_xor_sync(0xffffffffu, l1, 2);
            if ((lane & 3) == 0) {
                int r0 = mt2 * 32 + m2 * 16 + (lane >> 2);
                lg[r0 * 4 + nq] = l0;
                lg[(r0 + 8) * 4 + nq] = l1;
            }
        }
    }
    __syncthreads();

    if (tid < MT) {
        const float* lg = (const float*)(smem + SM_LOG);
        float l = lg[tid * 4] + lg[tid * 4 + 1] + lg[tid * 4 + 2] + lg[tid * 4 + 3] + b2v;
        int s = m0 + tid;
        ((float*)(smem + SM_SC))[tid] =
            (s < NS) ? sig_nat(l) * mask[b * NS + s] : 0.f;
    }
    __syncthreads();

    // ---- weighted partial sums: warp-cooperative, smem atomic reduce ----
    {
        const float* sc = (const float*)(smem + SM_SC);
        float* red = (float*)(smem + SM_RED);
        float acc[6];
#pragma unroll
        for (int j = 0; j < 6; ++j) acc[j] = 0.f;
#pragma unroll 2
        for (int i = 0; i < 8; ++i) {
            int r = wid * 8 + i;
            int s = m0 + r;
            if (s < NS) {
                float w = sc[r];
                const float* it = seq_items + ((long)b * NS + s) * 128;
                const float* ca = seq_cats + ((long)b * NS + s) * 64;
#pragma unroll
                for (int j = 0; j < 4; ++j) acc[j] += w * it[lane + 32 * j];
#pragma unroll
                for (int j = 4; j < 6; ++j) acc[j] += w * ca[lane + 32 * (j - 4)];
            }
        }
#pragma unroll
        for (int j = 0; j < 6; ++j) atomicAdd(red + lane + 32 * j, acc[j]);
    }
    __syncthreads();

    if (tid < 192) g_part[cta * 192 + tid] = ((const float*)(smem + SM_RED))[tid];
    if (tid < 32) {
        const float* sc = (const float*)(smem + SM_SC);
        float v = sc[tid] + sc[tid + 32];
#pragma unroll
        for (int o = 16; o; o >>= 1) v += __shfl_xor_sync(0xffffffffu, v, o);
        if (tid == 0) g_stot[cta] = v;
    }
}

__global__ void din_combine(float* __restrict__ out) {
    int b = blockIdx.x, c = threadIdx.x;   // 192 threads
    float w = g_part[(4 * b) * 192 + c] + g_part[(4 * b + 1) * 192 + c]
            + g_part[(4 * b + 2) * 192 + c] + g_part[(4 * b + 3) * 192 + c];
    float s = g_stot[4 * b] + g_stot[4 * b + 1] + g_stot[4 * b + 2] + g_stot[4 * b + 3];
    out[b * 192 + c] = w / (s + 1e-8f);
}

extern "C" void kernel_launch(void* const* d_in, const int* in_sizes, int n_in,
                              void* d_out, int out_size) {
    const float* item      = (const float*)d_in[0];
    const float* cat       = (const float*)d_in[1];
    const float* seq_items = (const float*)d_in[2];
    const float* seq_cats  = (const float*)d_in[3];
    const float* seq_times = (const float*)d_in[4];
    const float* seq_beh   = (const float*)d_in[5];
    const float* mask      = (const float*)d_in[6];
    const float* W1        = (const float*)d_in[7];
    const float* b1        = (const float*)d_in[8];
    const float* W2        = (const float*)d_in[9];
    const float* b2        = (const float*)d_in[10];
    float* out = (float*)d_out;

    static bool attr_done = false;
    if (!attr_done) {
        cudaFuncSetAttribute(din_mma5, cudaFuncAttributeMaxDynamicSharedMemorySize,
                             SMEM_BYTES);
        attr_done = true;
    }

    din_precompute_u<<<NB / 8, 256>>>(item, cat, W1, b1);
    din_wfrag<<<512, 32>>>(W1);
    din_packw2<<<1, 256>>>(W2, b2);

    float* w2b2;
    cudaGetSymbolAddress((void**)&w2b2, g_w2b2);
    din_mma5<<<NB * 4, 256, SMEM_BYTES>>>(seq_items, seq_cats, seq_times, seq_beh,
                                          mask, w2b2);
    din_combine<<<NB, 192>>>(out);
}

// round 17
// speedup vs baseline: 8.6450x; 1.1688x over previous
#include <cuda_runtime.h>
#include <cuda_fp16.h>
#include <cstdint>

// DIN attention pooling — HMMA fp16, A-resident SMEM, B fragment LDG (L1),
// tanh sigmoid, smem weighted-sum, bf double-buffer, merged prep.
// Inputs: 0 item[2048,128] 1 cat[2048,64] 2 seq_items[2048,200,128]
// 3 seq_cats[2048,200,64] 4 seq_times[2048,200,32] 5 seq_beh[2048,200,32]
// 6 mask[2048,200] 7 W1[448,256] 8 b1[256] 9 W2[256,1] 10 b2[1] -> out[2048,192]

#define NB 2048
#define NS 200
#define HID 256
#define MT 64                 // s-rows per CTA

#define ARS 528               // A row stride bytes (512B data + 16B pad)
#define A_RES (MT * ARS)      // 33792
#define SM_U   A_RES          // 256 f32
#define SM_W2  (SM_U + 1024)
#define SM_LOG (SM_W2 + 1024)          // 64 rows x 4 nq f32
#define SM_SC  (SM_LOG + 1024)         // 64 f32
#define SM_RED (SM_SC + 256)           // 192 f32
#define SMEM_BYTES (SM_RED + 768)      // 37888

// ---------------- global scratch ----------------
__device__ float g_U[NB * HID];
// B fragments: [n8(32)][k16(16)][lane(32)] -> uint2 {b0,b1}
__device__ __align__(16) uint2 g_Wf[32 * 16 * 32];
__device__ float g_part[NB * 4 * 192];
__device__ float g_stot[NB * 4];
__device__ float g_w2b2[257];

// ---------------- PTX helpers ----------------
__device__ __forceinline__ uint32_t smem_u32(const void* p) {
    uint32_t a;
    asm("{ .reg .u64 t; cvta.to.shared.u64 t, %1; cvt.u32.u64 %0, t; }"
        : "=r"(a) : "l"(p));
    return a;
}
__device__ __forceinline__ void ldsm_x4(uint32_t* r, uint32_t addr) {
    asm volatile("ldmatrix.sync.aligned.m8n8.x4.shared.b16 {%0,%1,%2,%3}, [%4];"
        : "=r"(r[0]), "=r"(r[1]), "=r"(r[2]), "=r"(r[3]) : "r"(addr));
}
__device__ __forceinline__ void mma_fp16(float* c, const uint32_t* a,
                                         uint32_t b0, uint32_t b1) {
    asm volatile(
        "mma.sync.aligned.m16n8k16.row.col.f32.f16.f16.f32 "
        "{%0,%1,%2,%3}, {%4,%5,%6,%7}, {%8,%9}, {%0,%1,%2,%3};"
        : "+f"(c[0]), "+f"(c[1]), "+f"(c[2]), "+f"(c[3])
        : "r"(a[0]), "r"(a[1]), "r"(a[2]), "r"(a[3]), "r"(b0), "r"(b1));
}
// sigmoid via single-MUFU tanh: sig(x) = 0.5*tanh(0.5x) + 0.5
__device__ __forceinline__ float sig_t(float x) {
    float t;
    asm("tanh.approx.f32 %0, %1;" : "=f"(t) : "f"(x * 0.5f));
    return fmaf(0.5f, t, 0.5f);
}

// feat gather: k in [0,256), regions k16-aligned
__device__ __forceinline__ float4 feat4(const float* it, const float* ca,
                                        const float* ti, const float* be,
                                        long row, int k) {
    if (k < 128) return *(const float4*)(it + row * 128 + k);
    if (k < 192) return *(const float4*)(ca + row * 64 + (k - 128));
    if (k < 224) return *(const float4*)(ti + row * 32 + (k - 192));
    return *(const float4*)(be + row * 32 + (k - 224));
}

// ---------------- merged prep kernel ----------------
// blocks 0..255: per-b U; 256..319: W fragments (8 tiles/block); 320: pack W2.
__global__ __launch_bounds__(256)
void din_prep(const float* __restrict__ item,
              const float* __restrict__ cat,
              const float* __restrict__ W1,
              const float* __restrict__ b1,
              const float* __restrict__ W2,
              const float* __restrict__ b2) {
    const int bid = blockIdx.x;
    const int tid = threadIdx.x;
    if (bid < 256) {
        __shared__ float sm[8][192];
        const int b0 = bid * 8;
        for (int i = tid; i < 8 * 192; i += 256) {
            int j = i / 192, k = i % 192;
            sm[j][k] = (k < 128) ? item[(b0 + j) * 128 + k]
                                 : cat[(b0 + j) * 64 + (k - 128)];
        }
        __syncthreads();
        const int h = tid;
        float acc[8];
        const float bias = b1[h];
#pragma unroll
        for (int j = 0; j < 8; ++j) acc[j] = bias;
        const float* wi = W1 + h;
        const float* wc = W1 + 256 * HID + h;
        for (int k = 0; k < 128; ++k) {
            float w = wi[k * HID];
#pragma unroll
            for (int j = 0; j < 8; ++j) acc[j] += w * sm[j][k];
        }
        for (int k = 0; k < 64; ++k) {
            float w = wc[k * HID];
#pragma unroll
            for (int j = 0; j < 8; ++j) acc[j] += w * sm[j][128 + k];
        }
#pragma unroll
        for (int j = 0; j < 8; ++j) g_U[(b0 + j) * HID + h] = acc[j];
    } else if (bid < 320) {
        // W fragment pack: tile = n8*16 + k16; lane t: n = n8*8 + t/4,
        // k0 = k16*16 + (t%4)*2; b0={W[n][k0],W[n][k0+1]}, b1={.. k0+8,k0+9}
        const int tile = (bid - 256) * 8 + (tid >> 5);
        const int lane = tid & 31;
        const int n8 = tile >> 4, k16 = tile & 15;
        const int n = n8 * 8 + (lane >> 2);
        const int k0 = k16 * 16 + (lane & 3) * 2;
        auto w = [&](int k) -> float {
            int row = (k < 128) ? (128 + k) : (192 + k);
            return W1[row * HID + n];
        };
        __half2 b0h = __floats2half2_rn(w(k0), w(k0 + 1));
        __half2 b1h = __floats2half2_rn(w(k0 + 8), w(k0 + 9));
        g_Wf[tile * 32 + lane] =
            make_uint2(*(const uint32_t*)&b0h, *(const uint32_t*)&b1h);
    } else {
        g_w2b2[tid] = W2[tid];
        if (tid == 0) g_w2b2[256] = b2[0];
    }
}

// ---------------- main kernel: CTA = 64 s-rows of one b ----------------
__global__ __launch_bounds__(256, 2)
void din_mma6(const float* __restrict__ seq_items,
              const float* __restrict__ seq_cats,
              const float* __restrict__ seq_times,
              const float* __restrict__ seq_beh,
              const float* __restrict__ mask,
              const float* __restrict__ b2p) {
    extern __shared__ char smem[];
    const uint32_t sb = smem_u32(smem);
    const int cta = blockIdx.x;
    const int b = cta >> 2;
    const int m0 = (cta & 3) * MT;
    const int tid = threadIdx.x;
    const int wid = tid >> 5;
    const int lane = tid & 31;
    const int mt2 = wid >> 2;    // m-half 0..1 (32 rows)
    const int nq = wid & 3;      // n-quarter 0..3 (64 cols)

    ((float*)(smem + SM_U))[tid] = g_U[b * HID + tid];
    ((float*)(smem + SM_W2))[tid] = b2p[tid];
    if (tid < 192) ((float*)(smem + SM_RED))[tid] = 0.f;
    const float b2v = b2p[256];

    // ---- A resident fill: 64 rows x 256 k -> fp16 ----
    {
        const int ar = tid >> 2, aq = tid & 3;
        const long arow = (long)b * NS + m0 + ar;
        const bool a_ok = (m0 + ar) < NS;
        char* abase = smem + ar * ARS + aq * 8;
#pragma unroll
        for (int kk = 0; kk < 16; ++kk) {
            float4 v = make_float4(0.f, 0.f, 0.f, 0.f);
            if (a_ok) v = feat4(seq_items, seq_cats, seq_times, seq_beh,
                                arow, kk * 16 + aq * 4);
            __half2 h0 = __floats2half2_rn(v.x, v.y);
            __half2 h1 = __floats2half2_rn(v.z, v.w);
            *(uint2*)(abase + kk * 32) =
                make_uint2(*(const uint32_t*)&h0, *(const uint32_t*)&h1);
        }
    }
    __syncthreads();

    float C[2][8][4];
#pragma unroll
    for (int m2 = 0; m2 < 2; ++m2)
#pragma unroll
        for (int p = 0; p < 8; ++p)
#pragma unroll
            for (int j = 0; j < 4; ++j) C[m2][p][j] = 0.f;

    const uint32_t a_off = sb + (uint32_t)((mt2 * 32 + (lane & 15)) * ARS
                                           + ((lane >> 4) << 4));
    const uint2* bf_base = g_Wf + (size_t)(nq * 8) * 16 * 32 + lane;

    // ---- mainloop: 16 k16 steps, bf double-buffered, no barriers ----
    uint2 bf0[8], bf1[8];
#pragma unroll
    for (int p = 0; p < 8; ++p) bf0[p] = __ldg(bf_base + (size_t)(p * 16) * 32);
#pragma unroll
    for (int kk = 0; kk < 16; ++kk) {
        uint2* cur = (kk & 1) ? bf1 : bf0;
        uint2* nxt = (kk & 1) ? bf0 : bf1;
        if (kk < 15) {
#pragma unroll
            for (int p = 0; p < 8; ++p)
                nxt[p] = __ldg(bf_base + (size_t)(p * 16 + kk + 1) * 32);
        }
        uint32_t a0[4], a1[4];
        ldsm_x4(a0, a_off + (uint32_t)(kk * 32));
        ldsm_x4(a1, a_off + (uint32_t)(16 * ARS + kk * 32));
#pragma unroll
        for (int p = 0; p < 8; ++p) {
            mma_fp16(C[0][p], a0, cur[p].x, cur[p].y);
            mma_fp16(C[1][p], a1, cur[p].x, cur[p].y);
        }
    }

    // ---- silu/W2 epilogue: per-row logits over this warp's n-quarter ----
    {
        const float* u_sm = (const float*)(smem + SM_U);
        const float* w2_sm = (const float*)(smem + SM_W2);
        float* lg = (float*)(smem + SM_LOG);
#pragma unroll
        for (int m2 = 0; m2 < 2; ++m2) {
            float l0 = 0.f, l1 = 0.f;
#pragma unroll
            for (int p = 0; p < 8; ++p) {
                int h0 = nq * 64 + p * 8 + (lane & 3) * 2;
                float2 uu = *(const float2*)(u_sm + h0);
                float2 ww = *(const float2*)(w2_sm + h0);
                float x0 = uu.x + C[m2][p][0], x1 = uu.y + C[m2][p][1];
                float x2 = uu.x + C[m2][p][2], x3 = uu.y + C[m2][p][3];
                l0 += x0 * sig_t(x0) * ww.x + x1 * sig_t(x1) * ww.y;
                l1 += x2 * sig_t(x2) * ww.x + x3 * sig_t(x3) * ww.y;
            }
            l0 += __shfl_xor_sync(0xffffffffu, l0, 1);
            l0 += __shfl_xor_sync(0xffffffffu, l0, 2);
            l1 += __shfl_xor_sync(0xffffffffu, l1, 1);
            l1 += __shfl_xor_sync(0xffffffffu, l1, 2);
            if ((lane & 3) == 0) {
                int r0 = mt2 * 32 + m2 * 16 + (lane >> 2);
                lg[r0 * 4 + nq] = l0;
                lg[(r0 + 8) * 4 + nq] = l1;
            }
        }
    }
    __syncthreads();

    if (tid < MT) {
        const float* lg = (const float*)(smem + SM_LOG);
        float l = lg[tid * 4] + lg[tid * 4 + 1] + lg[tid * 4 + 2] + lg[tid * 4 + 3] + b2v;
        int s = m0 + tid;
        ((float*)(smem + SM_SC))[tid] =
            (s < NS) ? sig_t(l) * mask[b * NS + s] : 0.f;
    }
    __syncthreads();

    // ---- weighted partial sums from resident A SMEM (fp16 feats) ----
    // thread covers dims (2*lane + 64j, 2*lane+1 + 64j), j=0..2 (dims 0..191)
    {
        const float* sc = (const float*)(smem + SM_SC);
        float* red = (float*)(smem + SM_RED);
        float2 acc[3];
#pragma unroll
        for (int j = 0; j < 3; ++j) acc[j] = make_float2(0.f, 0.f);
#pragma unroll 2
        for (int i = 0; i < 8; ++i) {
            int r = wid * 8 + i;
            float w = sc[r];
            const char* rowp = smem + r * ARS + 4 * lane;
#pragma unroll
            for (int j = 0; j < 3; ++j) {
                __half2 h = *(const __half2*)(rowp + 128 * j);
                float2 f = __half22float2(h);
                acc[j].x += w * f.x;
                acc[j].y += w * f.y;
            }
        }
#pragma unroll
        for (int j = 0; j < 3; ++j) {
            atomicAdd(red + 64 * j + 2 * lane, acc[j].x);
            atomicAdd(red + 64 * j + 2 * lane + 1, acc[j].y);
        }
    }
    __syncthreads();

    if (tid < 192) g_part[cta * 192 + tid] = ((const float*)(smem + SM_RED))[tid];
    if (tid < 32) {
        const float* sc = (const float*)(smem + SM_SC);
        float v = sc[tid] + sc[tid + 32];
#pragma unroll
        for (int o = 16; o; o >>= 1) v += __shfl_xor_sync(0xffffffffu, v, o);
        if (tid == 0) g_stot[cta] = v;
    }
}

__global__ void din_combine(float* __restrict__ out) {
    int b = blockIdx.x, c = threadIdx.x;   // 192 threads
    float w = g_part[(4 * b) * 192 + c] + g_part[(4 * b + 1) * 192 + c]
            + g_part[(4 * b + 2) * 192 + c] + g_part[(4 * b + 3) * 192 + c];
    float s = g_stot[4 * b] + g_stot[4 * b + 1] + g_stot[4 * b + 2] + g_stot[4 * b + 3];
    out[b * 192 + c] = w / (s + 1e-8f);
}

extern "C" void kernel_launch(void* const* d_in, const int* in_sizes, int n_in,
                              void* d_out, int out_size) {
    const float* item      = (const float*)d_in[0];
    const float* cat       = (const float*)d_in[1];
    const float* seq_items = (const float*)d_in[2];
    const float* seq_cats  = (const float*)d_in[3];
    const float* seq_times = (const float*)d_in[4];
    const float* seq_beh   = (const float*)d_in[5];
    const float* mask      = (const float*)d_in[6];
    const float* W1        = (const float*)d_in[7];
    const float* b1        = (const float*)d_in[8];
    const float* W2        = (const float*)d_in[9];
    const float* b2        = (const float*)d_in[10];
    float* out = (float*)d_out;

    static bool attr_done = false;
    if (!attr_done) {
        cudaFuncSetAttribute(din_mma6, cudaFuncAttributeMaxDynamicSharedMemorySize,
                             SMEM_BYTES);
        attr_done = true;
    }

    din_prep<<<321, 256>>>(item, cat, W1, b1, W2, b2);

    float* w2b2;
    cudaGetSymbolAddress((void**)&w2b2, g_w2b2);
    din_mma6<<<NB * 4, 256, SMEM_BYTES>>>(seq_items, seq_cats, seq_times, seq_beh,
                                          mask, w2b2);
    din_combine<<<NB, 192>>>(out);
}